// round 15
// baseline (speedup 1.0000x reference)
#include <cuda_runtime.h>
#include <cuda_bf16.h>
#include <cstdint>

#define NB 8
#define NP 2048
#define KNN 32
#define EPSBN 1e-5f
#define NEG_INF -3.402823466e38f

typedef __nv_bfloat16 bf16;

// ----------------- static device scratch (no runtime allocation) -----------------
__device__ float g_big[(size_t)NB*NP*NP];     // pdist2 gram (fp32)
__device__ bf16  g_ah[(size_t)NB*NP*NP];      // energy -> attn (bf16, in-place softmax)
__device__ int   g_idx[(size_t)NB*NP*KNN];
__device__ float g_xx[NB*NP];
__device__ float g_xs[(size_t)NB*128*NP];     // running SA features (fp32)
__device__ bf16  g_xsh[(size_t)NB*128*NP];
__device__ bf16  g_xsl[(size_t)NB*128*NP];
__device__ bf16  g_ch[(size_t)NB*512*NP];     // cat planes
__device__ bf16  g_cl[(size_t)NB*512*NP];
__device__ float g_pt[(size_t)NB*NP*64];
__device__ float g_qt[(size_t)NB*NP*64];
__device__ float g_eps1[(size_t)NB*NP*64];    // deterministic edge-conv stat partials
__device__ float g_eps2[(size_t)NB*NP*64];
__device__ bf16  g_qh[(size_t)NB*NP*32];      // q^T planes (point-major, lda=32)
__device__ bf16  g_ql[(size_t)NB*NP*32];
__device__ bf16  g_kh[(size_t)NB*32*NP];      // k planes [32][NP]
__device__ bf16  g_kl[(size_t)NB*32*NP];
__device__ float g_d[(size_t)NB*128*NP];      // t pre-BN
__device__ float g_t[(size_t)NB*128*NP];      // y = Wt @ xs (fp32)
__device__ bf16  g_yh[(size_t)NB*128*NP];
__device__ bf16  g_yl[(size_t)NB*128*NP];
__device__ float g_cs[NB*NP];
__device__ float g_tf[(size_t)NB*1024*NP];    // fuse pre-BN
__device__ float g_h1[(size_t)NB*512*NP];
__device__ bf16  g_h1h[(size_t)NB*512*NP];    // relu(bn(h1)) planes
__device__ bf16  g_h1l[(size_t)NB*512*NP];
__device__ float g_h2[(size_t)NB*256*NP];
__device__ float g_gm[NB*1024];
__device__ float g_w1g[NB*512];
__device__ bf16  g_wfh[1024*512]; __device__ bf16 g_wfl[1024*512];
__device__ bf16  g_w1h[512*512];  __device__ bf16 g_w1l[512*512];
__device__ bf16  g_w2h[256*512];  __device__ bf16 g_w2l[256*512];
__device__ bf16  g_wth[128*128];  __device__ bf16 g_wtl[128*128];
__device__ float g_mean[1024];
__device__ float g_istd[1024];

__device__ __forceinline__ float* bsel(int s){
  switch(s){
    case 0: return g_big;  case 1: return g_xs;
    case 11: return g_h2;  case 12: return g_xx;
  }
  return nullptr;
}

// ----------------- deterministic BN stats -----------------
// edge-conv: mean/istd per channel o from per-row partial sums (fixed order)
__global__ void edge_stats_kernel(float count){
  int o = blockIdx.x;
  int tid = threadIdx.x;
  __shared__ float sh1[256], sh2[256];
  float s1 = 0.f, s2 = 0.f;
  for (int r = tid; r < NB*NP; r += 256){
    s1 += g_eps1[(long)r*64 + o];
    s2 += g_eps2[(long)r*64 + o];
  }
  sh1[tid] = s1; sh2[tid] = s2;
  __syncthreads();
  for (int st = 128; st; st >>= 1){
    if (tid < st){ sh1[tid] += sh1[tid+st]; sh2[tid] += sh2[tid+st]; }
    __syncthreads();
  }
  if (tid == 0){
    float m = sh1[0] / count;
    float var = sh2[0] / count - m*m;
    g_mean[o] = m;
    g_istd[o] = rsqrtf(fmaxf(var, 0.f) + EPSBN);
  }
}

// generic: mean/istd per channel c over [b][C][NP] fp32 tensor (fixed order)
__global__ void chan_stats_kernel(const float* __restrict__ src, int C, float count){
  int c = blockIdx.x;
  int tid = threadIdx.x;
  __shared__ float sh1[256], sh2[256];
  float s1 = 0.f, s2 = 0.f;
  for (int b = 0; b < NB; b++){
    const float* p = src + ((long)b*C + c)*NP;
    for (int n = tid; n < NP; n += 256){ float v = p[n]; s1 += v; s2 += v*v; }
  }
  sh1[tid] = s1; sh2[tid] = s2;
  __syncthreads();
  for (int st = 128; st; st >>= 1){
    if (tid < st){ sh1[tid] += sh1[tid+st]; sh2[tid] += sh2[tid+st]; }
    __syncthreads();
  }
  if (tid == 0){
    float m = sh1[0] / count;
    float var = sh2[0] / count - m*m;
    g_mean[c] = m;
    g_istd[c] = rsqrtf(fmaxf(var, 0.f) + EPSBN);
  }
}

// ----------------- small utility kernels -----------------
__global__ void bn_relu_kernel(int dSel, long bstride, int C, int choff){
  float* data = bsel(dSel);
  long i = (long)blockIdx.x*blockDim.x + threadIdx.x;
  long tot = (long)NB*C*NP;
  if (i >= tot) return;
  int n = (int)(i % NP); long t = i / NP;
  int c = (int)(t % C);  int b = (int)(t / C);
  float* p = data + (long)b*bstride + (long)(choff+c)*NP + n;
  float v = (*p - g_mean[c]) * g_istd[c];
  *p = v > 0.f ? v : 0.f;
}

__global__ void bn_relu_planes_kernel(const float* __restrict__ src, int C,
                                      bf16* __restrict__ H, bf16* __restrict__ L){
  long i = (long)blockIdx.x*blockDim.x + threadIdx.x;
  long tot = (long)NB*C*NP;
  if (i >= tot) return;
  int c = (int)((i / NP) % C);
  float v = (src[i] - g_mean[c]) * g_istd[c];
  v = v > 0.f ? v : 0.f;
  bf16 hi = __float2bfloat16(v);
  H[i] = hi; L[i] = __float2bfloat16(v - __bfloat162float(hi));
}

__global__ void to_planes_kernel(const float* __restrict__ src, long total, int cols, int ld,
                                 bf16* __restrict__ H, bf16* __restrict__ L){
  long i = (long)blockIdx.x*256 + threadIdx.x;
  if (i >= total) return;
  long r = i / cols; int c = (int)(i % cols);
  float v = src[r*(long)ld + c];
  bf16 hi = __float2bfloat16(v);
  H[i] = hi; L[i] = __float2bfloat16(v - __bfloat162float(hi));
}

// ----------------- knn -----------------
// fused pdist+topk for xyz (C=3): x tile lives in smem; 8 rows per block
__global__ void knn1_kernel(const float* __restrict__ x){
  int b = blockIdx.x / (NP/8);
  int r0 = (blockIdx.x % (NP/8)) * 8;
  __shared__ float sx[3][NP];
  __shared__ float swv[8]; __shared__ int swi[8]; __shared__ int sbi;
  int tid = threadIdx.x;
  int lane = tid & 31, wid = tid >> 5;
  const float* xb = x + (long)b*3*NP;
  for (int i = tid; i < 3*NP; i += 256) sx[i/NP][i%NP] = xb[i];
  __syncthreads();
  for (int rr = 0; rr < 8; rr++){
    int n = r0 + rr;
    float cx = sx[0][n], cy = sx[1][n], cz = sx[2][n];
    float v[8];
    #pragma unroll
    for (int i = 0; i < 8; i++){
      int m = tid + i*256;
      float dx = sx[0][m]-cx, dy = sx[1][m]-cy, dz = sx[2][m]-cz;
      v[i] = -(dx*dx + dy*dy + dz*dz);
    }
    int* idxout = g_idx + ((long)(b*NP + n))*KNN;
    for (int it = 0; it < KNN; it++){
      float bv = v[0]; int bs = 0;
      #pragma unroll
      for (int i = 1; i < 8; i++) if (v[i] > bv){ bv = v[i]; bs = i; }
      int bidx = tid + bs*256;
      #pragma unroll
      for (int off = 16; off; off >>= 1){
        float ov = __shfl_down_sync(0xffffffffu, bv, off);
        int   oi = __shfl_down_sync(0xffffffffu, bidx, off);
        if (ov > bv || (ov == bv && oi < bidx)){ bv = ov; bidx = oi; }
      }
      if (lane == 0){ swv[wid] = bv; swi[wid] = bidx; }
      __syncthreads();
      if (tid == 0){
        float mv = swv[0]; int mi = swi[0];
        #pragma unroll
        for (int w = 1; w < 8; w++)
          if (swv[w] > mv || (swv[w] == mv && swi[w] < mi)){ mv = swv[w]; mi = swi[w]; }
        sbi = mi; idxout[it] = mi;
      }
      __syncthreads();
      int w = sbi;
      if ((w & 255) == tid) v[w >> 8] = NEG_INF;
    }
  }
}

// generic topk over fp32 rows of g_big (knn2)
__global__ void topk_kernel(){
  int row = blockIdx.x;
  const float* src = g_big + (long)row*NP;
  int tid = threadIdx.x;
  float v[8];
  #pragma unroll
  for (int i = 0; i < 8; i++) v[i] = src[tid + i*256];
  __shared__ float swv[8]; __shared__ int swi[8]; __shared__ int sbi;
  int lane = tid & 31, wid = tid >> 5;
  int* idxout = g_idx + (long)row*KNN;
  for (int it = 0; it < KNN; it++){
    float bv = v[0]; int bs = 0;
    #pragma unroll
    for (int i = 1; i < 8; i++) if (v[i] > bv){ bv = v[i]; bs = i; }
    int bidx = tid + bs*256;
    #pragma unroll
    for (int off = 16; off; off >>= 1){
      float ov = __shfl_down_sync(0xffffffffu, bv, off);
      int   oi = __shfl_down_sync(0xffffffffu, bidx, off);
      if (ov > bv || (ov == bv && oi < bidx)){ bv = ov; bidx = oi; }
    }
    if (lane == 0){ swv[wid] = bv; swi[wid] = bidx; }
    __syncthreads();
    if (tid == 0){
      float mv = swv[0]; int mi = swi[0];
      #pragma unroll
      for (int w = 1; w < 8; w++)
        if (swv[w] > mv || (swv[w] == mv && swi[w] < mi)){ mv = swv[w]; mi = swi[w]; }
      sbi = mi; idxout[it] = mi;
    }
    __syncthreads();
    int w = sbi;
    if ((w & 255) == tid) v[w >> 8] = NEG_INF;
  }
}

// ----------------- edge conv -----------------
__global__ void edge_pq_kernel(const float* __restrict__ fext, int fSel, long fbstride,
                               int C, const float* __restrict__ W){
  const float* f = (fSel >= 0) ? bsel(fSel) : fext;
  int b = blockIdx.y;
  int n0 = blockIdx.x*32;
  const float* fb = f + (long)b*fbstride;
  __shared__ float sf[64][32];
  int nl = threadIdx.x & 31, og = threadIdx.x >> 5;
  for (int c = og; c < C; c += 8) sf[c][nl] = fb[(long)c*NP + n0 + nl];
  __syncthreads();
  #pragma unroll
  for (int j = 0; j < 8; j++){
    int o = og*8 + j;
    const float* w = W + (long)o*2*C;
    float ap = 0.f, aq = 0.f;
    for (int c = 0; c < C; c++){
      float fv = sf[c][nl];
      ap += w[c]*fv;
      aq += (w[C+c]-w[c])*fv;
    }
    long off = ((long)(b*NP + n0 + nl))*64 + o;
    g_pt[off] = ap; g_qt[off] = aq;
  }
}

// emax + per-row deterministic stat partials (no atomics)
__global__ void edge_gather_kernel(int chbase){
  int row = blockIdx.x; int b = row / NP, n = row % NP;
  int o = threadIdx.x;
  __shared__ int sidx[KNN];
  if (o < KNN) sidx[o] = g_idx[(long)row*KNN + o];
  __syncthreads();
  float q = g_qt[(long)row*64 + o];
  float mx = NEG_INF, s1 = 0.f, s2 = 0.f;
  const float* pb = g_pt + (long)b*NP*64;
  #pragma unroll 4
  for (int k = 0; k < KNN; k++){
    float v = pb[(long)sidx[k]*64 + o] + q;
    mx = fmaxf(mx, v); s1 += v; s2 += v*v;
  }
  g_xs[((long)b*128 + chbase + o)*NP + n] = mx;
  g_eps1[(long)row*64 + o] = s1;
  g_eps2[(long)row*64 + o] = s2;
}

__global__ void sqnorm_kernel(){
  int i = blockIdx.x*blockDim.x + threadIdx.x;
  if (i >= NB*NP) return;
  int b = i / NP, n = i % NP;
  const float* f = g_xs + (long)b*128*NP + n;
  float s = 0.f;
  #pragma unroll 8
  for (int c = 0; c < 64; c++){ float v = f[(long)c*NP]; s += v*v; }
  g_xx[i] = s;
}

// ----------------- SA layer helpers -----------------
__global__ void qk_kernel(const float* __restrict__ Wq, const float* __restrict__ Wk,
                          bf16* __restrict__ qTh, bf16* __restrict__ qTl,
                          bf16* __restrict__ kh, bf16* __restrict__ kl){
  int b = blockIdx.y, n0 = blockIdx.x*32;
  __shared__ float sf[128][32];
  int nl = threadIdx.x & 31, og = threadIdx.x >> 5;
  const float* xb = g_xs + (long)b*128*NP;
  for (int c = og; c < 128; c += 8) sf[c][nl] = xb[(long)c*NP + n0 + nl];
  __syncthreads();
  #pragma unroll
  for (int j = 0; j < 4; j++){
    int qi = og*4 + j;
    const float* wq = Wq + qi*128;
    const float* wk = Wk + qi*128;
    float aq = 0.f, ak = 0.f;
    for (int c = 0; c < 128; c++){
      float fv = sf[c][nl];
      aq += wq[c]*fv; ak += wk[c]*fv;
    }
    bf16 qh = __float2bfloat16(aq);
    bf16 ql = __float2bfloat16(aq - __bfloat162float(qh));
    bf16 kh2 = __float2bfloat16(ak);
    bf16 kl2 = __float2bfloat16(ak - __bfloat162float(kh2));
    long qoff = ((long)b*NP + n0 + nl)*32 + qi;
    qTh[qoff] = qh; qTl[qoff] = ql;
    long koff = ((long)b*32 + qi)*NP + n0 + nl;
    kh[koff] = kh2; kl[koff] = kl2;
  }
}

// softmax IN PLACE on bf16 energy rows -> bf16 attn rows
__global__ void softmax_kernel(bf16* __restrict__ ah){
  long row = blockIdx.x;
  bf16* p = ah + row*(long)NP;
  int tid = threadIdx.x;
  int lane = tid & 31, wid = tid >> 5;
  __shared__ float sred[8];
  __shared__ float sres;
  float v[8];
  #pragma unroll
  for (int i = 0; i < 8; i++) v[i] = __bfloat162float(p[tid + i*256]);
  float m = v[0];
  #pragma unroll
  for (int i = 1; i < 8; i++) m = fmaxf(m, v[i]);
  #pragma unroll
  for (int off = 16; off; off >>= 1) m = fmaxf(m, __shfl_xor_sync(0xffffffffu, m, off));
  if (lane == 0) sred[wid] = m;
  __syncthreads();
  if (tid == 0){
    float t = sred[0];
    #pragma unroll
    for (int w = 1; w < 8; w++) t = fmaxf(t, sred[w]);
    sres = t;
  }
  __syncthreads();
  float bmax = sres;
  float s = 0.f;
  #pragma unroll
  for (int i = 0; i < 8; i++){ v[i] = __expf(v[i] - bmax); s += v[i]; }
  #pragma unroll
  for (int off = 16; off; off >>= 1) s += __shfl_xor_sync(0xffffffffu, s, off);
  __syncthreads();
  if (lane == 0) sred[wid] = s;
  __syncthreads();
  if (tid == 0){
    float t = 0.f;
    #pragma unroll
    for (int w = 0; w < 8; w++) t += sred[w];
    sres = t;
  }
  __syncthreads();
  float inv = 1.f / sres;
  #pragma unroll
  for (int i = 0; i < 8; i++)
    p[tid + i*256] = __float2bfloat16(v[i]*inv);
}

// column sums of attn (2 bf16 columns per thread via 32-bit loads)
__global__ void colsum_kernel(const bf16* __restrict__ ah){
  int b = blockIdx.y;
  int m2 = blockIdx.x*256 + threadIdx.x;
  const __nv_bfloat162* A = (const __nv_bfloat162*)(ah + (long)b*NP*NP) + m2;
  float s0 = 0.f, s1 = 0.f;
  for (int n = 0; n < NP; n++){
    float2 f = __bfloat1622float2(A[(long)n*(NP/2)]);
    s0 += f.x; s1 += f.y;
  }
  g_cs[b*NP + 2*m2    ] = 1.f / (1e-6f + s0);
  g_cs[b*NP + 2*m2 + 1] = 1.f / (1e-6f + s1);
}

// residual: xs += relu(bn(t)); write xs planes + cat plane slice
__global__ void residual_kernel(int layer,
                                bf16* __restrict__ xsh, bf16* __restrict__ xsl,
                                bf16* __restrict__ ch, bf16* __restrict__ cl){
  long i = (long)blockIdx.x*blockDim.x + threadIdx.x;
  long tot = (long)NB*128*NP;
  if (i >= tot) return;
  int n = (int)(i % NP); long t = i / NP;
  int c = (int)(t % 128); int b = (int)(t / 128);
  long xi = ((long)b*128 + c)*NP + n;
  float tv = g_d[xi];
  float r = (tv - g_mean[c]) * g_istd[c];
  r = r > 0.f ? r : 0.f;
  float v = g_xs[xi] + r;
  g_xs[xi] = v;
  bf16 hi = __float2bfloat16(v);
  bf16 lo = __float2bfloat16(v - __bfloat162float(hi));
  xsh[xi] = hi; xsl[xi] = lo;
  long ci = ((long)b*512 + layer*128 + c)*NP + n;
  ch[ci] = hi; cl[ci] = lo;
}

// ----------------- fuse / head helpers -----------------
__global__ void gmax_kernel(){
  int row = blockIdx.x;
  int o = row & 1023;
  const float* p = g_tf + (long)row*NP;
  float m = NEG_INF;
  for (int n = threadIdx.x; n < NP; n += 128) m = fmaxf(m, p[n]);
  #pragma unroll
  for (int off = 16; off; off >>= 1) m = fmaxf(m, __shfl_xor_sync(0xffffffffu, m, off));
  __shared__ float sw[4];
  int lane = threadIdx.x & 31, wid = threadIdx.x >> 5;
  if (lane == 0) sw[wid] = m;
  __syncthreads();
  if (threadIdx.x == 0){
    float mm = fmaxf(fmaxf(sw[0], sw[1]), fmaxf(sw[2], sw[3]));
    float v = (mm - g_mean[o]) * g_istd[o];
    g_gm[row] = v > 0.f ? v : 0.f;
  }
}

__global__ void w1g_kernel(const float* __restrict__ Wc1){
  int o = blockIdx.x*8 + (threadIdx.x >> 5);
  int lane = threadIdx.x & 31;
  const float* w = Wc1 + (long)o*1536;
  float acc[NB];
  #pragma unroll
  for (int b = 0; b < NB; b++) acc[b] = 0.f;
  for (int c = lane; c < 1024; c += 32){
    float wv = w[c];
    #pragma unroll
    for (int b = 0; b < NB; b++) acc[b] += wv * g_gm[b*1024 + c];
  }
  #pragma unroll
  for (int b = 0; b < NB; b++){
    #pragma unroll
    for (int off = 16; off; off >>= 1) acc[b] += __shfl_xor_sync(0xffffffffu, acc[b], off);
  }
  if (lane == 0){
    #pragma unroll
    for (int b = 0; b < NB; b++) g_w1g[b*512 + o] = acc[b];
  }
}

// ----------------- tensor-core bf16-split GEMM -----------------
__device__ __forceinline__ uint32_t smem_u32(const void* p){
  return (uint32_t)__cvta_generic_to_shared(p);
}
__device__ __forceinline__ void ldm_x4(uint32_t a, uint32_t &r0, uint32_t &r1, uint32_t &r2, uint32_t &r3){
  asm volatile("ldmatrix.sync.aligned.m8n8.x4.shared.b16 {%0,%1,%2,%3}, [%4];"
    : "=r"(r0),"=r"(r1),"=r"(r2),"=r"(r3) : "r"(a));
}
__device__ __forceinline__ void ldm_x4t(uint32_t a, uint32_t &r0, uint32_t &r1, uint32_t &r2, uint32_t &r3){
  asm volatile("ldmatrix.sync.aligned.m8n8.x4.trans.shared.b16 {%0,%1,%2,%3}, [%4];"
    : "=r"(r0),"=r"(r1),"=r"(r2),"=r"(r3) : "r"(a));
}
__device__ __forceinline__ void mma16816(float* d, const uint32_t* a, const uint32_t* b){
  asm volatile("mma.sync.aligned.m16n8k16.row.col.f32.bf16.bf16.f32 "
    "{%0,%1,%2,%3}, {%4,%5,%6,%7}, {%8,%9}, {%0,%1,%2,%3};"
    : "+f"(d[0]),"+f"(d[1]),"+f"(d[2]),"+f"(d[3])
    : "r"(a[0]),"r"(a[1]),"r"(a[2]),"r"(a[3]), "r"(b[0]),"r"(b[1]));
}

// C[b](M x 2048) = A[b](M x K, hi/lo planes, lda) * B[b](K x 2048, ldb=NP)
// EPI: 0 plain, 4 rowbias(E1[b][row]), 6 xr: v=E1[row*NP+col]-a*E2[col]
// POUT: 0 = fp32 C only; 1 = fp32 C + bf16 hi/lo planes; 2 = bf16 hi plane ONLY
// BLO: B has a lo plane (3-product split) or hi only (2 products)
template<int EPI, int POUT, bool BLO>
__global__ void __launch_bounds__(256)
mma_gemm(int M, int K,
  const bf16* __restrict__ Ah, const bf16* __restrict__ Al, int lda, long sA,
  const bf16* __restrict__ Bh, const bf16* __restrict__ Bl, long sB,
  float* __restrict__ Cc, int ldc, long sC,
  bf16* __restrict__ Ph, bf16* __restrict__ Pl,
  const float* __restrict__ E1, long se1,
  const float* __restrict__ E2, long se2)
{
  __shared__ bf16 As[2][128][40];
  __shared__ bf16 Bs[BLO ? 2 : 1][32][136];
  int bb = blockIdx.z;
  const bf16* Ap[2] = {Ah + (long)bb*sA, Al + (long)bb*sA};
  const bf16* Bp0 = Bh + (long)bb*sB;
  const bf16* Bp1 = BLO ? (Bl + (long)bb*sB) : nullptr;
  float* C = Cc + (long)bb*sC;
  const float* e1 = nullptr; const float* e2 = nullptr;
  if (EPI == 4 || EPI == 6) e1 = E1 + (long)bb*se1;
  if (EPI == 6) e2 = E2 + (long)bb*se2;

  int tm = blockIdx.y*128, tn = blockIdx.x*128;
  int tid = threadIdx.x, lane = tid & 31, wid = tid >> 5;
  int wm = wid >> 2, wn = wid & 3;

  float acc[4][4][4];
  #pragma unroll
  for (int i = 0; i < 4; i++)
    #pragma unroll
    for (int j = 0; j < 4; j++)
      #pragma unroll
      for (int u = 0; u < 4; u++) acc[i][j][u] = 0.f;

  int fr = lane & 15, fs = lane >> 4;

  for (int k0 = 0; k0 < K; k0 += 32){
    #pragma unroll
    for (int l = 0; l < 4; l++){
      int li = tid + l*256;
      int p = li >> 9, s = li & 511;
      int r = s >> 2, seg = (s & 3)*8;
      uint4 v = *(const uint4*)&Ap[p][(long)(tm + r)*lda + k0 + seg];
      *(uint4*)&As[p][r][seg] = v;
    }
    {
      constexpr int NBL = BLO ? 4 : 2;
      #pragma unroll
      for (int l = 0; l < NBL; l++){
        int li = tid + l*256;
        int p = li >> 9, s = li & 511;
        int kk = s >> 4, seg = (s & 15)*8;
        const bf16* src = (p == 0) ? Bp0 : Bp1;
        uint4 v = *(const uint4*)&src[(long)(k0 + kk)*NP + tn + seg];
        *(uint4*)&Bs[p][kk][seg] = v;
      }
    }
    __syncthreads();
    #pragma unroll
    for (int ks = 0; ks < 2; ks++){
      uint32_t aF[2][4][4], bF[2][4][2];
      #pragma unroll
      for (int p = 0; p < 2; p++){
        #pragma unroll
        for (int i = 0; i < 4; i++){
          uint32_t ad = smem_u32(&As[p][wm*64 + i*16 + fr][ks*16 + fs*8]);
          ldm_x4(ad, aF[p][i][0], aF[p][i][1], aF[p][i][2], aF[p][i][3]);
        }
      }
      constexpr int NBP = BLO ? 2 : 1;
      #pragma unroll
      for (int p = 0; p < NBP; p++){
        #pragma unroll
        for (int j2 = 0; j2 < 2; j2++){
          uint32_t ad = smem_u32(&Bs[p][ks*16 + fr][wn*32 + j2*16 + fs*8]);
          ldm_x4t(ad, bF[p][j2*2][0], bF[p][j2*2][1], bF[p][j2*2+1][0], bF[p][j2*2+1][1]);
        }
      }
      #pragma unroll
      for (int i = 0; i < 4; i++)
        #pragma unroll
        for (int j = 0; j < 4; j++){
          mma16816(acc[i][j], aF[0][i], bF[0][j]);
          if (BLO) mma16816(acc[i][j], aF[0][i], bF[1][j]);
          mma16816(acc[i][j], aF[1][i], bF[0][j]);
        }
    }
    __syncthreads();
  }

  int gr = lane >> 2, cp = (lane & 3)*2;
  #pragma unroll
  for (int i = 0; i < 4; i++){
    #pragma unroll
    for (int h = 0; h < 2; h++){
      int row = tm + wm*64 + i*16 + gr + h*8;
      float rowbias = (EPI == 4) ? e1[row] : 0.f;
      #pragma unroll
      for (int j = 0; j < 4; j++){
        int col = tn + wn*32 + j*8 + cp;
        #pragma unroll
        for (int u = 0; u < 2; u++){
          float v = acc[i][j][h*2 + u];
          int cc = col + u;
          if (EPI == 6) v = e1[(long)row*NP + cc] - v*e2[cc];
          else v += rowbias;
          if (POUT != 2) C[(long)row*ldc + cc] = v;
          if (POUT == 1){
            bf16 hi = __float2bfloat16(v);
            long po = (long)bb*sC + (long)row*ldc + cc;
            Ph[po] = hi; Pl[po] = __float2bfloat16(v - __bfloat162float(hi));
          } else if (POUT == 2){
            long po = (long)bb*sC + (long)row*ldc + cc;
            Ph[po] = __float2bfloat16(v);
          }
        }
      }
    }
  }
}

// ----------------- fp32 tiled SGEMM (pdist2 gram + final Wc3 only) -----------------
template<int EPI, bool TRANSA>
__global__ void __launch_bounds__(256)
gemm_kernel(int M, int K,
  const float* __restrict__ Aext, int aSel, int lda, long sA,
  int bSel, int ldb, long sB,
  float* __restrict__ Cext, int cSel, int ldc, long sC,
  const float* __restrict__ e1ext, int e1Sel, long se1,
  int e2Sel, long se2)
{
  int bb = blockIdx.z;
  const float* A = ((aSel >= 0) ? bsel(aSel) : Aext) + (long)bb*sA;
  const float* B = bsel(bSel) + (long)bb*sB;
  float* C = ((cSel >= 0) ? bsel(cSel) : Cext) + (long)bb*sC;
  const float* E1 = nullptr;
  if (EPI == 1 || EPI == 5)
    E1 = ((e1Sel >= 0) ? bsel(e1Sel) : e1ext) + (long)bb*se1;

  int tm = blockIdx.y*64, tn = blockIdx.x*128;
  __shared__ float As[32][68];
  __shared__ float Bs[32][128];
  int tid = threadIdx.x;
  int tx = tid & 15, ty = tid >> 4;
  float acc[4][8] = {};

  for (int k0 = 0; k0 < K; k0 += 32){
    if (TRANSA){
      int kk = tid >> 4, mm = (tid & 15)*4;
      *(float4*)&As[kk   ][mm] = *(const float4*)&A[(long)(k0+kk   )*lda + tm + mm];
      *(float4*)&As[kk+16][mm] = *(const float4*)&A[(long)(k0+kk+16)*lda + tm + mm];
    } else {
      int rl = tid >> 2, kk = (tid & 3)*8;
      int row = tm + rl;
      float4 a0 = make_float4(0.f,0.f,0.f,0.f), a1 = a0;
      if (row < M){
        a0 = *(const float4*)&A[(long)row*lda + k0 + kk];
        a1 = *(const float4*)&A[(long)row*lda + k0 + kk + 4];
      }
      As[kk  ][rl] = a0.x; As[kk+1][rl] = a0.y; As[kk+2][rl] = a0.z; As[kk+3][rl] = a0.w;
      As[kk+4][rl] = a1.x; As[kk+5][rl] = a1.y; As[kk+6][rl] = a1.z; As[kk+7][rl] = a1.w;
    }
    {
      int kb = tid >> 4, nn = (tid & 15)*4;
      *(float4*)&Bs[kb   ][nn   ] = *(const float4*)&B[(long)(k0+kb   )*ldb + tn + nn];
      *(float4*)&Bs[kb   ][nn+64] = *(const float4*)&B[(long)(k0+kb   )*ldb + tn + nn + 64];
      *(float4*)&Bs[kb+16][nn   ] = *(const float4*)&B[(long)(k0+kb+16)*ldb + tn + nn];
      *(float4*)&Bs[kb+16][nn+64] = *(const float4*)&B[(long)(k0+kb+16)*ldb + tn + nn + 64];
    }
    __syncthreads();
    #pragma unroll
    for (int kk = 0; kk < 32; kk++){
      float4 a4 = *(float4*)&As[kk][ty*4];
      float4 b0 = *(float4*)&Bs[kk][tx*4];
      float4 b1 = *(float4*)&Bs[kk][64 + tx*4];
      float ar[4] = {a4.x, a4.y, a4.z, a4.w};
      float br[8] = {b0.x, b0.y, b0.z, b0.w, b1.x, b1.y, b1.z, b1.w};
      #pragma unroll
      for (int i = 0; i < 4; i++)
        #pragma unroll
        for (int j = 0; j < 8; j++)
          acc[i][j] += ar[i]*br[j];
    }
    __syncthreads();
  }

  int c0 = tn + tx*4, c1 = tn + 64 + tx*4;
  #pragma unroll
  for (int i = 0; i < 4; i++){
    int row = tm + ty*4 + i;
    bool ok = row < M;
    float bias = 0.f;
    if (EPI == 5 && ok) bias = E1[row];
    float out[8];
    #pragma unroll
    for (int j = 0; j < 8; j++){
      int col = (j < 4) ? (c0 + j) : (c1 + j - 4);
      float v = acc[i][j];
      if (EPI == 1) v = 2.f*v - (ok ? E1[row] : 0.f) - E1[col];
      else          v += bias;
      out[j] = v;
    }
    if (ok){
      *(float4*)&C[(long)row*ldc + c0] = make_float4(out[0],out[1],out[2],out[3]);
      *(float4*)&C[(long)row*ldc + c1] = make_float4(out[4],out[5],out[6],out[7]);
    }
  }
}

// ----------------- host orchestration -----------------
#define SYMADDR(var, sym) void* var##_v; cudaGetSymbolAddress(&var##_v, sym);
extern "C" void kernel_launch(void* const* d_in, const int* in_sizes, int n_in,
                              void* d_out, int out_size) {
  (void)in_sizes; (void)n_in; (void)out_size;
  const float* x   = (const float*)d_in[0];
  const float* We1 = (const float*)d_in[1];
  const float* We2 = (const float*)d_in[3];
  const float* Wq  = (const float*)d_in[5];
  const float* Wk  = (const float*)d_in[6];
  const float* Wt  = (const float*)d_in[7];
  const float* Wf  = (const float*)d_in[9];
  const float* Wc1 = (const float*)d_in[11];
  const float* Wc2 = (const float*)d_in[13];
  const float* Wc3 = (const float*)d_in[15];
  const float* bc3 = (const float*)d_in[16];
  float* out = (float*)d_out;

  SYMADDR(ah, g_ah)
  SYMADDR(xsh, g_xsh) SYMADDR(xsl, g_xsl)
  SYMADDR(ch, g_ch)   SYMADDR(cl, g_cl)
  SYMADDR(qh, g_qh)   SYMADDR(ql, g_ql)
  SYMADDR(kh, g_kh)   SYMADDR(kl, g_kl)
  SYMADDR(yh, g_yh)   SYMADDR(yl, g_yl)
  SYMADDR(h1h, g_h1h) SYMADDR(h1l, g_h1l)
  SYMADDR(wfh, g_wfh) SYMADDR(wfl, g_wfl)
  SYMADDR(w1h, g_w1h) SYMADDR(w1l, g_w1l)
  SYMADDR(w2h, g_w2h) SYMADDR(w2l, g_w2l)
  SYMADDR(wth, g_wth) SYMADDR(wtl, g_wtl)
  SYMADDR(xs, g_xs)   SYMADDR(big, g_big)
  SYMADDR(tb, g_t)    SYMADDR(db, g_d)
  SYMADDR(cs, g_cs)   SYMADDR(tf, g_tf)
  SYMADDR(h1, g_h1)   SYMADDR(h2, g_h2)
  SYMADDR(w1gp, g_w1g)
  bf16 *p_ah=(bf16*)ah_v, *p_xsh=(bf16*)xsh_v, *p_xsl=(bf16*)xsl_v;
  bf16 *p_ch=(bf16*)ch_v, *p_cl=(bf16*)cl_v, *p_qh=(bf16*)qh_v, *p_ql=(bf16*)ql_v;
  bf16 *p_kh=(bf16*)kh_v, *p_kl=(bf16*)kl_v;
  bf16 *p_yh=(bf16*)yh_v, *p_yl=(bf16*)yl_v, *p_h1h=(bf16*)h1h_v, *p_h1l=(bf16*)h1l_v;
  bf16 *p_wfh=(bf16*)wfh_v, *p_wfl=(bf16*)wfl_v, *p_w1h=(bf16*)w1h_v, *p_w1l=(bf16*)w1l_v;
  bf16 *p_w2h=(bf16*)w2h_v, *p_w2l=(bf16*)w2l_v, *p_wth=(bf16*)wth_v, *p_wtl=(bf16*)wtl_v;
  float *p_xs=(float*)xs_v, *p_big=(float*)big_v, *p_t=(float*)tb_v, *p_d=(float*)db_v;
  float *p_cs=(float*)cs_v, *p_tf=(float*)tf_v, *p_h1=(float*)h1_v, *p_h2=(float*)h2_v;
  float *p_w1g=(float*)w1gp_v;

  const long SBIG = (long)NP*NP;
  const long SXS  = (long)128*NP;

  // weight planes (deterministic each call)
  to_planes_kernel<<<(1024*512+255)/256, 256>>>(Wf, 1024*512, 512, 512, p_wfh, p_wfl);
  to_planes_kernel<<<(512*512+255)/256, 256>>>(Wc1 + 1024, 512*512, 512, 1536, p_w1h, p_w1l);
  to_planes_kernel<<<(256*512+255)/256, 256>>>(Wc2, 256*512, 512, 512, p_w2h, p_w2l);

  // ---- knn on xyz (fused pdist+topk) + edgeconv1 ----
  knn1_kernel<<<NB*(NP/8), 256>>>(x);
  edge_pq_kernel<<<dim3(NP/32, NB), 256>>>(x, -1, (long)3*NP, 3, We1);
  edge_gather_kernel<<<NB*NP, 64>>>(0);
  edge_stats_kernel<<<64, 256>>>((float)((long)NB*NP*KNN));
  bn_relu_kernel<<<(NB*64*NP)/256, 256>>>(1, SXS, 64, 0);

  // ---- knn on f1 (fp32 gram — preserves neighbor selection) + edgeconv2 ----
  sqnorm_kernel<<<(NB*NP)/256, 256>>>();
  gemm_kernel<1, true><<<dim3(16, 32, NB), 256>>>(NP, 64,
      nullptr, 1, NP, SXS, 1, NP, SXS,
      nullptr, 0, NP, SBIG, nullptr, 12, NP, -1, 0);
  topk_kernel<<<NB*NP, 256>>>();
  edge_pq_kernel<<<dim3(NP/32, NB), 256>>>(nullptr, 1, SXS, 64, We2);
  edge_gather_kernel<<<NB*NP, 64>>>(64);
  edge_stats_kernel<<<64, 256>>>((float)((long)NB*NP*KNN));
  bn_relu_kernel<<<(NB*64*NP)/256, 256>>>(1, SXS, 64, 64);

  // xs planes (layer-0 input)
  to_planes_kernel<<<((long)NB*128*NP+255)/256, 256>>>(p_xs, (long)NB*128*NP, NP, NP, p_xsh, p_xsl);

  // ---- 4 SA layers ----
  for (int i = 0; i < 4; i++){
    qk_kernel<<<dim3(NP/32, NB), 256>>>(Wq + (long)i*32*128, Wk + (long)i*32*128,
                                        p_qh, p_ql, p_kh, p_kl);
    // energy = qT @ k  (M=2048, K=32) -> bf16 hi plane only
    mma_gemm<0, 2, true><<<dim3(16, 16, NB), 256>>>(NP, 32,
        p_qh, p_ql, 32, (long)NP*32,
        p_kh, p_kl, (long)32*NP,
        p_big, NP, SBIG,
        p_ah, nullptr, nullptr, 0, nullptr, 0);
    softmax_kernel<<<NB*NP, 256>>>(p_ah);
    colsum_kernel<<<dim3(NP/512, NB), 256>>>(p_ah);
    // y = Wt @ xs  (also emit y planes)
    to_planes_kernel<<<(128*128+255)/256, 256>>>(Wt + (long)i*128*128, 128*128, 128, 128, p_wth, p_wtl);
    mma_gemm<0, 1, true><<<dim3(16, 1, NB), 256>>>(128, 128,
        p_wth, p_wtl, 128, 0,
        p_xsh, p_xsl, SXS,
        p_t, NP, SXS,
        p_yh, p_yl, nullptr, 0, nullptr, 0);
    // t = y - (y @ attn) * cs ; attn hi-only
    mma_gemm<6, 0, false><<<dim3(16, 1, NB), 256>>>(128, NP,
        p_yh, p_yl, NP, SXS,
        p_ah, p_ah, SBIG,
        p_d, NP, SXS,
        nullptr, nullptr, p_t, SXS, p_cs, NP);
    chan_stats_kernel<<<128, 256>>>(p_d, 128, (float)(NB*NP));
    residual_kernel<<<(NB*128*NP)/256, 256>>>(i, p_xsh, p_xsl, p_ch, p_cl);
  }

  // ---- fuse + global max ----
  mma_gemm<0, 0, true><<<dim3(16, 8, NB), 256>>>(1024, 512,
      p_wfh, p_wfl, 512, 0,
      p_ch, p_cl, (long)512*NP,
      p_tf, NP, (long)1024*NP,
      nullptr, nullptr, nullptr, 0, nullptr, 0);
  chan_stats_kernel<<<1024, 256>>>(p_tf, 1024, (float)(NB*NP));
  gmax_kernel<<<NB*1024, 128>>>();
  w1g_kernel<<<64, 256>>>(Wc1);

  // ---- head ----
  mma_gemm<4, 0, true><<<dim3(16, 4, NB), 256>>>(512, 512,
      p_w1h, p_w1l, 512, 0,
      p_ch, p_cl, (long)512*NP,
      p_h1, NP, (long)512*NP,
      nullptr, nullptr, p_w1g, 512, nullptr, 0);
  chan_stats_kernel<<<512, 256>>>(p_h1, 512, (float)(NB*NP));
  bn_relu_planes_kernel<<<((long)NB*512*NP)/256, 256>>>(p_h1, 512, p_h1h, p_h1l);

  mma_gemm<0, 0, true><<<dim3(16, 2, NB), 256>>>(256, 512,
      p_w2h, p_w2l, 512, 0,
      p_h1h, p_h1l, (long)512*NP,
      p_h2, NP, (long)256*NP,
      nullptr, nullptr, nullptr, 0, nullptr, 0);
  chan_stats_kernel<<<256, 256>>>(p_h2, 256, (float)(NB*NP));
  bn_relu_kernel<<<(NB*256*NP)/256, 256>>>(11, (long)256*NP, 256, 0);

  gemm_kernel<5, false><<<dim3(16, 1, NB), 256>>>(13, 256,
      Wc3, -1, 256, 0, 11, NP, (long)256*NP,
      out, -1, NP, (long)13*NP, bc3, -1, 0, -1, 0);
}

// round 16
// speedup vs baseline: 1.6640x; 1.6640x over previous
#include <cuda_runtime.h>
#include <cuda_bf16.h>
#include <cstdint>

#define NB 8
#define NP 2048
#define KNN 32
#define EPSBN 1e-5f
#define NEG_INF -3.402823466e38f

typedef __nv_bfloat16 bf16;

// ----------------- static device scratch (no runtime allocation) -----------------
__device__ float g_big[(size_t)NB*NP*NP];     // pdist2 gram (fp32)
__device__ bf16  g_ah[(size_t)NB*NP*NP];      // energy -> attn (bf16, in-place softmax)
__device__ int   g_idx[(size_t)NB*NP*KNN];
__device__ float g_xx[NB*NP];
__device__ float g_xs[(size_t)NB*128*NP];     // running SA features (fp32)
__device__ bf16  g_xsh[(size_t)NB*128*NP];
__device__ bf16  g_xsl[(size_t)NB*128*NP];
__device__ bf16  g_ch[(size_t)NB*512*NP];     // cat planes
__device__ bf16  g_cl[(size_t)NB*512*NP];
__device__ float g_pt[(size_t)NB*NP*64];
__device__ float g_qt[(size_t)NB*NP*64];
__device__ float g_eps1[(size_t)64*NB*NP];    // stat partials, [o][row] (coalesced read)
__device__ float g_eps2[(size_t)64*NB*NP];
__device__ bf16  g_qh[(size_t)NB*NP*32];      // q^T planes (point-major, lda=32)
__device__ bf16  g_ql[(size_t)NB*NP*32];
__device__ bf16  g_kh[(size_t)NB*32*NP];      // k planes [32][NP]
__device__ bf16  g_kl[(size_t)NB*32*NP];
__device__ float g_d[(size_t)NB*128*NP];      // t pre-BN
__device__ float g_t[(size_t)NB*128*NP];      // y = Wt @ xs (fp32)
__device__ bf16  g_yh[(size_t)NB*128*NP];
__device__ bf16  g_yl[(size_t)NB*128*NP];
__device__ float g_cs[NB*NP];
__device__ float g_tf[(size_t)NB*1024*NP];    // fuse pre-BN
__device__ float g_h1[(size_t)NB*512*NP];
__device__ bf16  g_h1h[(size_t)NB*512*NP];    // relu(bn(h1)) planes
__device__ bf16  g_h1l[(size_t)NB*512*NP];
__device__ float g_h2[(size_t)NB*256*NP];
__device__ float g_gm[NB*1024];
__device__ float g_w1g[NB*512];
__device__ bf16  g_wfh[1024*512]; __device__ bf16 g_wfl[1024*512];
__device__ bf16  g_w1h[512*512];  __device__ bf16 g_w1l[512*512];
__device__ bf16  g_w2h[256*512];  __device__ bf16 g_w2l[256*512];
__device__ bf16  g_wth[128*128];  __device__ bf16 g_wtl[128*128];
__device__ float g_mean[1024];
__device__ float g_istd[1024];

__device__ __forceinline__ float* bsel(int s){
  switch(s){
    case 0: return g_big;  case 1: return g_xs;
    case 11: return g_h2;  case 12: return g_xx;
  }
  return nullptr;
}

// ----------------- deterministic BN stats -----------------
// edge-conv: mean/istd per channel o from per-row partial sums ([o][row] layout, coalesced)
__global__ void edge_stats_kernel(float count){
  int o = blockIdx.x;
  int tid = threadIdx.x;
  __shared__ float sh1[256], sh2[256];
  const float* e1 = g_eps1 + (long)o*(NB*NP);
  const float* e2 = g_eps2 + (long)o*(NB*NP);
  float s1 = 0.f, s2 = 0.f;
  for (int r = tid; r < NB*NP; r += 256){
    s1 += e1[r];
    s2 += e2[r];
  }
  sh1[tid] = s1; sh2[tid] = s2;
  __syncthreads();
  for (int st = 128; st; st >>= 1){
    if (tid < st){ sh1[tid] += sh1[tid+st]; sh2[tid] += sh2[tid+st]; }
    __syncthreads();
  }
  if (tid == 0){
    float m = sh1[0] / count;
    float var = sh2[0] / count - m*m;
    g_mean[o] = m;
    g_istd[o] = rsqrtf(fmaxf(var, 0.f) + EPSBN);
  }
}

// generic: mean/istd per channel c over [b][C][NP] fp32 tensor (fixed order)
__global__ void chan_stats_kernel(const float* __restrict__ src, int C, float count){
  int c = blockIdx.x;
  int tid = threadIdx.x;
  __shared__ float sh1[256], sh2[256];
  float s1 = 0.f, s2 = 0.f;
  for (int b = 0; b < NB; b++){
    const float* p = src + ((long)b*C + c)*NP;
    for (int n = tid; n < NP; n += 256){ float v = p[n]; s1 += v; s2 += v*v; }
  }
  sh1[tid] = s1; sh2[tid] = s2;
  __syncthreads();
  for (int st = 128; st; st >>= 1){
    if (tid < st){ sh1[tid] += sh1[tid+st]; sh2[tid] += sh2[tid+st]; }
    __syncthreads();
  }
  if (tid == 0){
    float m = sh1[0] / count;
    float var = sh2[0] / count - m*m;
    g_mean[c] = m;
    g_istd[c] = rsqrtf(fmaxf(var, 0.f) + EPSBN);
  }
}

// ----------------- small utility kernels -----------------
__global__ void bn_relu_kernel(int dSel, long bstride, int C, int choff){
  float* data = bsel(dSel);
  long i = (long)blockIdx.x*blockDim.x + threadIdx.x;
  long tot = (long)NB*C*NP;
  if (i >= tot) return;
  int n = (int)(i % NP); long t = i / NP;
  int c = (int)(t % C);  int b = (int)(t / C);
  float* p = data + (long)b*bstride + (long)(choff+c)*NP + n;
  float v = (*p - g_mean[c]) * g_istd[c];
  *p = v > 0.f ? v : 0.f;
}

__global__ void bn_relu_planes_kernel(const float* __restrict__ src, int C,
                                      bf16* __restrict__ H, bf16* __restrict__ L){
  long i = (long)blockIdx.x*blockDim.x + threadIdx.x;
  long tot = (long)NB*C*NP;
  if (i >= tot) return;
  int c = (int)((i / NP) % C);
  float v = (src[i] - g_mean[c]) * g_istd[c];
  v = v > 0.f ? v : 0.f;
  bf16 hi = __float2bfloat16(v);
  H[i] = hi; L[i] = __float2bfloat16(v - __bfloat162float(hi));
}

__global__ void to_planes_kernel(const float* __restrict__ src, long total, int cols, int ld,
                                 bf16* __restrict__ H, bf16* __restrict__ L){
  long i = (long)blockIdx.x*256 + threadIdx.x;
  if (i >= total) return;
  long r = i / cols; int c = (int)(i % cols);
  float v = src[r*(long)ld + c];
  bf16 hi = __float2bfloat16(v);
  H[i] = hi; L[i] = __float2bfloat16(v - __bfloat162float(hi));
}

// ----------------- knn -----------------
// fused pdist+topk for xyz (C=3): x tile in smem; ONE row per block (full parallelism)
__global__ void knn1_kernel(const float* __restrict__ x){
  int b = blockIdx.x / NP;
  int n = blockIdx.x % NP;
  __shared__ float sx[3][NP];
  __shared__ float swv[8]; __shared__ int swi[8]; __shared__ int sbi;
  int tid = threadIdx.x;
  int lane = tid & 31, wid = tid >> 5;
  const float* xb = x + (long)b*3*NP;
  for (int i = tid; i < 3*NP; i += 256) sx[i/NP][i%NP] = xb[i];
  __syncthreads();
  float cx = sx[0][n], cy = sx[1][n], cz = sx[2][n];
  float v[8];
  #pragma unroll
  for (int i = 0; i < 8; i++){
    int m = tid + i*256;
    float dx = sx[0][m]-cx, dy = sx[1][m]-cy, dz = sx[2][m]-cz;
    v[i] = -(dx*dx + dy*dy + dz*dz);
  }
  int* idxout = g_idx + ((long)(b*NP + n))*KNN;
  for (int it = 0; it < KNN; it++){
    float bv = v[0]; int bs = 0;
    #pragma unroll
    for (int i = 1; i < 8; i++) if (v[i] > bv){ bv = v[i]; bs = i; }
    int bidx = tid + bs*256;
    #pragma unroll
    for (int off = 16; off; off >>= 1){
      float ov = __shfl_down_sync(0xffffffffu, bv, off);
      int   oi = __shfl_down_sync(0xffffffffu, bidx, off);
      if (ov > bv || (ov == bv && oi < bidx)){ bv = ov; bidx = oi; }
    }
    if (lane == 0){ swv[wid] = bv; swi[wid] = bidx; }
    __syncthreads();
    if (tid == 0){
      float mv = swv[0]; int mi = swi[0];
      #pragma unroll
      for (int w = 1; w < 8; w++)
        if (swv[w] > mv || (swv[w] == mv && swi[w] < mi)){ mv = swv[w]; mi = swi[w]; }
      sbi = mi; idxout[it] = mi;
    }
    __syncthreads();
    int w = sbi;
    if ((w & 255) == tid) v[w >> 8] = NEG_INF;
  }
}

// generic topk over fp32 rows of g_big (knn2)
__global__ void topk_kernel(){
  int row = blockIdx.x;
  const float* src = g_big + (long)row*NP;
  int tid = threadIdx.x;
  float v[8];
  #pragma unroll
  for (int i = 0; i < 8; i++) v[i] = src[tid + i*256];
  __shared__ float swv[8]; __shared__ int swi[8]; __shared__ int sbi;
  int lane = tid & 31, wid = tid >> 5;
  int* idxout = g_idx + (long)row*KNN;
  for (int it = 0; it < KNN; it++){
    float bv = v[0]; int bs = 0;
    #pragma unroll
    for (int i = 1; i < 8; i++) if (v[i] > bv){ bv = v[i]; bs = i; }
    int bidx = tid + bs*256;
    #pragma unroll
    for (int off = 16; off; off >>= 1){
      float ov = __shfl_down_sync(0xffffffffu, bv, off);
      int   oi = __shfl_down_sync(0xffffffffu, bidx, off);
      if (ov > bv || (ov == bv && oi < bidx)){ bv = ov; bidx = oi; }
    }
    if (lane == 0){ swv[wid] = bv; swi[wid] = bidx; }
    __syncthreads();
    if (tid == 0){
      float mv = swv[0]; int mi = swi[0];
      #pragma unroll
      for (int w = 1; w < 8; w++)
        if (swv[w] > mv || (swv[w] == mv && swi[w] < mi)){ mv = swv[w]; mi = swi[w]; }
      sbi = mi; idxout[it] = mi;
    }
    __syncthreads();
    int w = sbi;
    if ((w & 255) == tid) v[w >> 8] = NEG_INF;
  }
}

// ----------------- edge conv -----------------
__global__ void edge_pq_kernel(const float* __restrict__ fext, int fSel, long fbstride,
                               int C, const float* __restrict__ W){
  const float* f = (fSel >= 0) ? bsel(fSel) : fext;
  int b = blockIdx.y;
  int n0 = blockIdx.x*32;
  const float* fb = f + (long)b*fbstride;
  __shared__ float sf[64][32];
  int nl = threadIdx.x & 31, og = threadIdx.x >> 5;
  for (int c = og; c < C; c += 8) sf[c][nl] = fb[(long)c*NP + n0 + nl];
  __syncthreads();
  #pragma unroll
  for (int j = 0; j < 8; j++){
    int o = og*8 + j;
    const float* w = W + (long)o*2*C;
    float ap = 0.f, aq = 0.f;
    for (int c = 0; c < C; c++){
      float fv = sf[c][nl];
      ap += w[c]*fv;
      aq += (w[C+c]-w[c])*fv;
    }
    long off = ((long)(b*NP + n0 + nl))*64 + o;
    g_pt[off] = ap; g_qt[off] = aq;
  }
}

// emax + per-row deterministic stat partials (no atomics; [o][row] layout)
__global__ void edge_gather_kernel(int chbase){
  int row = blockIdx.x; int b = row / NP, n = row % NP;
  int o = threadIdx.x;
  __shared__ int sidx[KNN];
  if (o < KNN) sidx[o] = g_idx[(long)row*KNN + o];
  __syncthreads();
  float q = g_qt[(long)row*64 + o];
  float mx = NEG_INF, s1 = 0.f, s2 = 0.f;
  const float* pb = g_pt + (long)b*NP*64;
  #pragma unroll 4
  for (int k = 0; k < KNN; k++){
    float v = pb[(long)sidx[k]*64 + o] + q;
    mx = fmaxf(mx, v); s1 += v; s2 += v*v;
  }
  g_xs[((long)b*128 + chbase + o)*NP + n] = mx;
  g_eps1[(long)o*(NB*NP) + row] = s1;
  g_eps2[(long)o*(NB*NP) + row] = s2;
}

__global__ void sqnorm_kernel(){
  int i = blockIdx.x*blockDim.x + threadIdx.x;
  if (i >= NB*NP) return;
  int b = i / NP, n = i % NP;
  const float* f = g_xs + (long)b*128*NP + n;
  float s = 0.f;
  #pragma unroll 8
  for (int c = 0; c < 64; c++){ float v = f[(long)c*NP]; s += v*v; }
  g_xx[i] = s;
}

// ----------------- SA layer helpers -----------------
__global__ void qk_kernel(const float* __restrict__ Wq, const float* __restrict__ Wk,
                          bf16* __restrict__ qTh, bf16* __restrict__ qTl,
                          bf16* __restrict__ kh, bf16* __restrict__ kl){
  int b = blockIdx.y, n0 = blockIdx.x*32;
  __shared__ float sf[128][32];
  int nl = threadIdx.x & 31, og = threadIdx.x >> 5;
  const float* xb = g_xs + (long)b*128*NP;
  for (int c = og; c < 128; c += 8) sf[c][nl] = xb[(long)c*NP + n0 + nl];
  __syncthreads();
  #pragma unroll
  for (int j = 0; j < 4; j++){
    int qi = og*4 + j;
    const float* wq = Wq + qi*128;
    const float* wk = Wk + qi*128;
    float aq = 0.f, ak = 0.f;
    for (int c = 0; c < 128; c++){
      float fv = sf[c][nl];
      aq += wq[c]*fv; ak += wk[c]*fv;
    }
    bf16 qh = __float2bfloat16(aq);
    bf16 ql = __float2bfloat16(aq - __bfloat162float(qh));
    bf16 kh2 = __float2bfloat16(ak);
    bf16 kl2 = __float2bfloat16(ak - __bfloat162float(kh2));
    long qoff = ((long)b*NP + n0 + nl)*32 + qi;
    qTh[qoff] = qh; qTl[qoff] = ql;
    long koff = ((long)b*32 + qi)*NP + n0 + nl;
    kh[koff] = kh2; kl[koff] = kl2;
  }
}

// softmax IN PLACE on bf16 energy rows -> bf16 attn rows
__global__ void softmax_kernel(bf16* __restrict__ ah){
  long row = blockIdx.x;
  bf16* p = ah + row*(long)NP;
  int tid = threadIdx.x;
  int lane = tid & 31, wid = tid >> 5;
  __shared__ float sred[8];
  __shared__ float sres;
  float v[8];
  #pragma unroll
  for (int i = 0; i < 8; i++) v[i] = __bfloat162float(p[tid + i*256]);
  float m = v[0];
  #pragma unroll
  for (int i = 1; i < 8; i++) m = fmaxf(m, v[i]);
  #pragma unroll
  for (int off = 16; off; off >>= 1) m = fmaxf(m, __shfl_xor_sync(0xffffffffu, m, off));
  if (lane == 0) sred[wid] = m;
  __syncthreads();
  if (tid == 0){
    float t = sred[0];
    #pragma unroll
    for (int w = 1; w < 8; w++) t = fmaxf(t, sred[w]);
    sres = t;
  }
  __syncthreads();
  float bmax = sres;
  float s = 0.f;
  #pragma unroll
  for (int i = 0; i < 8; i++){ v[i] = __expf(v[i] - bmax); s += v[i]; }
  #pragma unroll
  for (int off = 16; off; off >>= 1) s += __shfl_xor_sync(0xffffffffu, s, off);
  __syncthreads();
  if (lane == 0) sred[wid] = s;
  __syncthreads();
  if (tid == 0){
    float t = 0.f;
    #pragma unroll
    for (int w = 0; w < 8; w++) t += sred[w];
    sres = t;
  }
  __syncthreads();
  float inv = 1.f / sres;
  #pragma unroll
  for (int i = 0; i < 8; i++)
    p[tid + i*256] = __float2bfloat16(v[i]*inv);
}

// column sums of attn: 128 columns per block, 4-way n-split, fixed-order combine
__global__ void colsum_kernel(const bf16* __restrict__ ah){
  int b = blockIdx.y;
  int cp = threadIdx.x & 63;            // column-pair within block
  int ns = threadIdx.x >> 6;            // n-slice 0..3
  int m2 = blockIdx.x*64 + cp;          // global column-pair index
  const __nv_bfloat162* A = (const __nv_bfloat162*)(ah + (long)b*NP*NP) + m2;
  float s0 = 0.f, s1 = 0.f;
  int nbeg = ns*512, nend = nbeg + 512;
  for (int n = nbeg; n < nend; n++){
    float2 f = __bfloat1622float2(A[(long)n*(NP/2)]);
    s0 += f.x; s1 += f.y;
  }
  __shared__ float sh[4][64][2];
  sh[ns][cp][0] = s0; sh[ns][cp][1] = s1;
  __syncthreads();
  if (ns == 0){
    float t0 = (sh[0][cp][0] + sh[1][cp][0]) + (sh[2][cp][0] + sh[3][cp][0]);
    float t1 = (sh[0][cp][1] + sh[1][cp][1]) + (sh[2][cp][1] + sh[3][cp][1]);
    g_cs[b*NP + 2*m2    ] = 1.f / (1e-6f + t0);
    g_cs[b*NP + 2*m2 + 1] = 1.f / (1e-6f + t1);
  }
}

// residual: xs += relu(bn(t)); write xs planes + cat plane slice
__global__ void residual_kernel(int layer,
                                bf16* __restrict__ xsh, bf16* __restrict__ xsl,
                                bf16* __restrict__ ch, bf16* __restrict__ cl){
  long i = (long)blockIdx.x*blockDim.x + threadIdx.x;
  long tot = (long)NB*128*NP;
  if (i >= tot) return;
  int n = (int)(i % NP); long t = i / NP;
  int c = (int)(t % 128); int b = (int)(t / 128);
  long xi = ((long)b*128 + c)*NP + n;
  float tv = g_d[xi];
  float r = (tv - g_mean[c]) * g_istd[c];
  r = r > 0.f ? r : 0.f;
  float v = g_xs[xi] + r;
  g_xs[xi] = v;
  bf16 hi = __float2bfloat16(v);
  bf16 lo = __float2bfloat16(v - __bfloat162float(hi));
  xsh[xi] = hi; xsl[xi] = lo;
  long ci = ((long)b*512 + layer*128 + c)*NP + n;
  ch[ci] = hi; cl[ci] = lo;
}

// ----------------- fuse / head helpers -----------------
__global__ void gmax_kernel(){
  int row = blockIdx.x;
  int o = row & 1023;
  const float* p = g_tf + (long)row*NP;
  float m = NEG_INF;
  for (int n = threadIdx.x; n < NP; n += 128) m = fmaxf(m, p[n]);
  #pragma unroll
  for (int off = 16; off; off >>= 1) m = fmaxf(m, __shfl_xor_sync(0xffffffffu, m, off));
  __shared__ float sw[4];
  int lane = threadIdx.x & 31, wid = threadIdx.x >> 5;
  if (lane == 0) sw[wid] = m;
  __syncthreads();
  if (threadIdx.x == 0){
    float mm = fmaxf(fmaxf(sw[0], sw[1]), fmaxf(sw[2], sw[3]));
    float v = (mm - g_mean[o]) * g_istd[o];
    g_gm[row] = v > 0.f ? v : 0.f;
  }
}

__global__ void w1g_kernel(const float* __restrict__ Wc1){
  int o = blockIdx.x*8 + (threadIdx.x >> 5);
  int lane = threadIdx.x & 31;
  const float* w = Wc1 + (long)o*1536;
  float acc[NB];
  #pragma unroll
  for (int b = 0; b < NB; b++) acc[b] = 0.f;
  for (int c = lane; c < 1024; c += 32){
    float wv = w[c];
    #pragma unroll
    for (int b = 0; b < NB; b++) acc[b] += wv * g_gm[b*1024 + c];
  }
  #pragma unroll
  for (int b = 0; b < NB; b++){
    #pragma unroll
    for (int off = 16; off; off >>= 1) acc[b] += __shfl_xor_sync(0xffffffffu, acc[b], off);
  }
  if (lane == 0){
    #pragma unroll
    for (int b = 0; b < NB; b++) g_w1g[b*512 + o] = acc[b];
  }
}

// ----------------- tensor-core bf16-split GEMM -----------------
__device__ __forceinline__ uint32_t smem_u32(const void* p){
  return (uint32_t)__cvta_generic_to_shared(p);
}
__device__ __forceinline__ void ldm_x4(uint32_t a, uint32_t &r0, uint32_t &r1, uint32_t &r2, uint32_t &r3){
  asm volatile("ldmatrix.sync.aligned.m8n8.x4.shared.b16 {%0,%1,%2,%3}, [%4];"
    : "=r"(r0),"=r"(r1),"=r"(r2),"=r"(r3) : "r"(a));
}
__device__ __forceinline__ void ldm_x4t(uint32_t a, uint32_t &r0, uint32_t &r1, uint32_t &r2, uint32_t &r3){
  asm volatile("ldmatrix.sync.aligned.m8n8.x4.trans.shared.b16 {%0,%1,%2,%3}, [%4];"
    : "=r"(r0),"=r"(r1),"=r"(r2),"=r"(r3) : "r"(a));
}
__device__ __forceinline__ void mma16816(float* d, const uint32_t* a, const uint32_t* b){
  asm volatile("mma.sync.aligned.m16n8k16.row.col.f32.bf16.bf16.f32 "
    "{%0,%1,%2,%3}, {%4,%5,%6,%7}, {%8,%9}, {%0,%1,%2,%3};"
    : "+f"(d[0]),"+f"(d[1]),"+f"(d[2]),"+f"(d[3])
    : "r"(a[0]),"r"(a[1]),"r"(a[2]),"r"(a[3]), "r"(b[0]),"r"(b[1]));
}

// C[b](M x 2048) = A[b](M x K, hi/lo planes, lda) * B[b](K x 2048, ldb=NP)
// EPI: 0 plain, 4 rowbias(E1[b][row]), 6 xr: v=E1[row*NP+col]-a*E2[col]
// POUT: 0 = fp32 C only; 1 = fp32 C + bf16 hi/lo planes; 2 = bf16 hi plane ONLY
// BLO: B has a lo plane (3-product split) or hi only (2 products)
template<int EPI, int POUT, bool BLO>
__global__ void __launch_bounds__(256)
mma_gemm(int M, int K,
  const bf16* __restrict__ Ah, const bf16* __restrict__ Al, int lda, long sA,
  const bf16* __restrict__ Bh, const bf16* __restrict__ Bl, long sB,
  float* __restrict__ Cc, int ldc, long sC,
  bf16* __restrict__ Ph, bf16* __restrict__ Pl,
  const float* __restrict__ E1, long se1,
  const float* __restrict__ E2, long se2)
{
  __shared__ bf16 As[2][128][40];
  __shared__ bf16 Bs[BLO ? 2 : 1][32][136];
  int bb = blockIdx.z;
  const bf16* Ap[2] = {Ah + (long)bb*sA, Al + (long)bb*sA};
  const bf16* Bp0 = Bh + (long)bb*sB;
  const bf16* Bp1 = BLO ? (Bl + (long)bb*sB) : nullptr;
  float* C = Cc + (long)bb*sC;
  const float* e1 = nullptr; const float* e2 = nullptr;
  if (EPI == 4 || EPI == 6) e1 = E1 + (long)bb*se1;
  if (EPI == 6) e2 = E2 + (long)bb*se2;

  int tm = blockIdx.y*128, tn = blockIdx.x*128;
  int tid = threadIdx.x, lane = tid & 31, wid = tid >> 5;
  int wm = wid >> 2, wn = wid & 3;

  float acc[4][4][4];
  #pragma unroll
  for (int i = 0; i < 4; i++)
    #pragma unroll
    for (int j = 0; j < 4; j++)
      #pragma unroll
      for (int u = 0; u < 4; u++) acc[i][j][u] = 0.f;

  int fr = lane & 15, fs = lane >> 4;

  for (int k0 = 0; k0 < K; k0 += 32){
    #pragma unroll
    for (int l = 0; l < 4; l++){
      int li = tid + l*256;
      int p = li >> 9, s = li & 511;
      int r = s >> 2, seg = (s & 3)*8;
      uint4 v = *(const uint4*)&Ap[p][(long)(tm + r)*lda + k0 + seg];
      *(uint4*)&As[p][r][seg] = v;
    }
    {
      constexpr int NBL = BLO ? 4 : 2;
      #pragma unroll
      for (int l = 0; l < NBL; l++){
        int li = tid + l*256;
        int p = li >> 9, s = li & 511;
        int kk = s >> 4, seg = (s & 15)*8;
        const bf16* src = (p == 0) ? Bp0 : Bp1;
        uint4 v = *(const uint4*)&src[(long)(k0 + kk)*NP + tn + seg];
        *(uint4*)&Bs[p][kk][seg] = v;
      }
    }
    __syncthreads();
    #pragma unroll
    for (int ks = 0; ks < 2; ks++){
      uint32_t aF[2][4][4], bF[2][4][2];
      #pragma unroll
      for (int p = 0; p < 2; p++){
        #pragma unroll
        for (int i = 0; i < 4; i++){
          uint32_t ad = smem_u32(&As[p][wm*64 + i*16 + fr][ks*16 + fs*8]);
          ldm_x4(ad, aF[p][i][0], aF[p][i][1], aF[p][i][2], aF[p][i][3]);
        }
      }
      constexpr int NBP = BLO ? 2 : 1;
      #pragma unroll
      for (int p = 0; p < NBP; p++){
        #pragma unroll
        for (int j2 = 0; j2 < 2; j2++){
          uint32_t ad = smem_u32(&Bs[p][ks*16 + fr][wn*32 + j2*16 + fs*8]);
          ldm_x4t(ad, bF[p][j2*2][0], bF[p][j2*2][1], bF[p][j2*2+1][0], bF[p][j2*2+1][1]);
        }
      }
      #pragma unroll
      for (int i = 0; i < 4; i++)
        #pragma unroll
        for (int j = 0; j < 4; j++){
          mma16816(acc[i][j], aF[0][i], bF[0][j]);
          if (BLO) mma16816(acc[i][j], aF[0][i], bF[1][j]);
          mma16816(acc[i][j], aF[1][i], bF[0][j]);
        }
    }
    __syncthreads();
  }

  int gr = lane >> 2, cp = (lane & 3)*2;
  #pragma unroll
  for (int i = 0; i < 4; i++){
    #pragma unroll
    for (int h = 0; h < 2; h++){
      int row = tm + wm*64 + i*16 + gr + h*8;
      float rowbias = (EPI == 4) ? e1[row] : 0.f;
      #pragma unroll
      for (int j = 0; j < 4; j++){
        int col = tn + wn*32 + j*8 + cp;
        #pragma unroll
        for (int u = 0; u < 2; u++){
          float v = acc[i][j][h*2 + u];
          int cc = col + u;
          if (EPI == 6) v = e1[(long)row*NP + cc] - v*e2[cc];
          else v += rowbias;
          if (POUT != 2) C[(long)row*ldc + cc] = v;
          if (POUT == 1){
            bf16 hi = __float2bfloat16(v);
            long po = (long)bb*sC + (long)row*ldc + cc;
            Ph[po] = hi; Pl[po] = __float2bfloat16(v - __bfloat162float(hi));
          } else if (POUT == 2){
            long po = (long)bb*sC + (long)row*ldc + cc;
            Ph[po] = __float2bfloat16(v);
          }
        }
      }
    }
  }
}

// ----------------- fp32 tiled SGEMM (pdist2 gram + final Wc3 only) -----------------
template<int EPI, bool TRANSA>
__global__ void __launch_bounds__(256)
gemm_kernel(int M, int K,
  const float* __restrict__ Aext, int aSel, int lda, long sA,
  int bSel, int ldb, long sB,
  float* __restrict__ Cext, int cSel, int ldc, long sC,
  const float* __restrict__ e1ext, int e1Sel, long se1,
  int e2Sel, long se2)
{
  int bb = blockIdx.z;
  const float* A = ((aSel >= 0) ? bsel(aSel) : Aext) + (long)bb*sA;
  const float* B = bsel(bSel) + (long)bb*sB;
  float* C = ((cSel >= 0) ? bsel(cSel) : Cext) + (long)bb*sC;
  const float* E1 = nullptr;
  if (EPI == 1 || EPI == 5)
    E1 = ((e1Sel >= 0) ? bsel(e1Sel) : e1ext) + (long)bb*se1;

  int tm = blockIdx.y*64, tn = blockIdx.x*128;
  __shared__ float As[32][68];
  __shared__ float Bs[32][128];
  int tid = threadIdx.x;
  int tx = tid & 15, ty = tid >> 4;
  float acc[4][8] = {};

  for (int k0 = 0; k0 < K; k0 += 32){
    if (TRANSA){
      int kk = tid >> 4, mm = (tid & 15)*4;
      *(float4*)&As[kk   ][mm] = *(const float4*)&A[(long)(k0+kk   )*lda + tm + mm];
      *(float4*)&As[kk+16][mm] = *(const float4*)&A[(long)(k0+kk+16)*lda + tm + mm];
    } else {
      int rl = tid >> 2, kk = (tid & 3)*8;
      int row = tm + rl;
      float4 a0 = make_float4(0.f,0.f,0.f,0.f), a1 = a0;
      if (row < M){
        a0 = *(const float4*)&A[(long)row*lda + k0 + kk];
        a1 = *(const float4*)&A[(long)row*lda + k0 + kk + 4];
      }
      As[kk  ][rl] = a0.x; As[kk+1][rl] = a0.y; As[kk+2][rl] = a0.z; As[kk+3][rl] = a0.w;
      As[kk+4][rl] = a1.x; As[kk+5][rl] = a1.y; As[kk+6][rl] = a1.z; As[kk+7][rl] = a1.w;
    }
    {
      int kb = tid >> 4, nn = (tid & 15)*4;
      *(float4*)&Bs[kb   ][nn   ] = *(const float4*)&B[(long)(k0+kb   )*ldb + tn + nn];
      *(float4*)&Bs[kb   ][nn+64] = *(const float4*)&B[(long)(k0+kb   )*ldb + tn + nn + 64];
      *(float4*)&Bs[kb+16][nn   ] = *(const float4*)&B[(long)(k0+kb+16)*ldb + tn + nn];
      *(float4*)&Bs[kb+16][nn+64] = *(const float4*)&B[(long)(k0+kb+16)*ldb + tn + nn + 64];
    }
    __syncthreads();
    #pragma unroll
    for (int kk = 0; kk < 32; kk++){
      float4 a4 = *(float4*)&As[kk][ty*4];
      float4 b0 = *(float4*)&Bs[kk][tx*4];
      float4 b1 = *(float4*)&Bs[kk][64 + tx*4];
      float ar[4] = {a4.x, a4.y, a4.z, a4.w};
      float br[8] = {b0.x, b0.y, b0.z, b0.w, b1.x, b1.y, b1.z, b1.w};
      #pragma unroll
      for (int i = 0; i < 4; i++)
        #pragma unroll
        for (int j = 0; j < 8; j++)
          acc[i][j] += ar[i]*br[j];
    }
    __syncthreads();
  }

  int c0 = tn + tx*4, c1 = tn + 64 + tx*4;
  #pragma unroll
  for (int i = 0; i < 4; i++){
    int row = tm + ty*4 + i;
    bool ok = row < M;
    float bias = 0.f;
    if (EPI == 5 && ok) bias = E1[row];
    float out[8];
    #pragma unroll
    for (int j = 0; j < 8; j++){
      int col = (j < 4) ? (c0 + j) : (c1 + j - 4);
      float v = acc[i][j];
      if (EPI == 1) v = 2.f*v - (ok ? E1[row] : 0.f) - E1[col];
      else          v += bias;
      out[j] = v;
    }
    if (ok){
      *(float4*)&C[(long)row*ldc + c0] = make_float4(out[0],out[1],out[2],out[3]);
      *(float4*)&C[(long)row*ldc + c1] = make_float4(out[4],out[5],out[6],out[7]);
    }
  }
}

// ----------------- host orchestration -----------------
#define SYMADDR(var, sym) void* var##_v; cudaGetSymbolAddress(&var##_v, sym);
extern "C" void kernel_launch(void* const* d_in, const int* in_sizes, int n_in,
                              void* d_out, int out_size) {
  (void)in_sizes; (void)n_in; (void)out_size;
  const float* x   = (const float*)d_in[0];
  const float* We1 = (const float*)d_in[1];
  const float* We2 = (const float*)d_in[3];
  const float* Wq  = (const float*)d_in[5];
  const float* Wk  = (const float*)d_in[6];
  const float* Wt  = (const float*)d_in[7];
  const float* Wf  = (const float*)d_in[9];
  const float* Wc1 = (const float*)d_in[11];
  const float* Wc2 = (const float*)d_in[13];
  const float* Wc3 = (const float*)d_in[15];
  const float* bc3 = (const float*)d_in[16];
  float* out = (float*)d_out;

  SYMADDR(ah, g_ah)
  SYMADDR(xsh, g_xsh) SYMADDR(xsl, g_xsl)
  SYMADDR(ch, g_ch)   SYMADDR(cl, g_cl)
  SYMADDR(qh, g_qh)   SYMADDR(ql, g_ql)
  SYMADDR(kh, g_kh)   SYMADDR(kl, g_kl)
  SYMADDR(yh, g_yh)   SYMADDR(yl, g_yl)
  SYMADDR(h1h, g_h1h) SYMADDR(h1l, g_h1l)
  SYMADDR(wfh, g_wfh) SYMADDR(wfl, g_wfl)
  SYMADDR(w1h, g_w1h) SYMADDR(w1l, g_w1l)
  SYMADDR(w2h, g_w2h) SYMADDR(w2l, g_w2l)
  SYMADDR(wth, g_wth) SYMADDR(wtl, g_wtl)
  SYMADDR(xs, g_xs)   SYMADDR(big, g_big)
  SYMADDR(tb, g_t)    SYMADDR(db, g_d)
  SYMADDR(cs, g_cs)   SYMADDR(tf, g_tf)
  SYMADDR(h1, g_h1)   SYMADDR(h2, g_h2)
  SYMADDR(w1gp, g_w1g)
  bf16 *p_ah=(bf16*)ah_v, *p_xsh=(bf16*)xsh_v, *p_xsl=(bf16*)xsl_v;
  bf16 *p_ch=(bf16*)ch_v, *p_cl=(bf16*)cl_v, *p_qh=(bf16*)qh_v, *p_ql=(bf16*)ql_v;
  bf16 *p_kh=(bf16*)kh_v, *p_kl=(bf16*)kl_v;
  bf16 *p_yh=(bf16*)yh_v, *p_yl=(bf16*)yl_v, *p_h1h=(bf16*)h1h_v, *p_h1l=(bf16*)h1l_v;
  bf16 *p_wfh=(bf16*)wfh_v, *p_wfl=(bf16*)wfl_v, *p_w1h=(bf16*)w1h_v, *p_w1l=(bf16*)w1l_v;
  bf16 *p_w2h=(bf16*)w2h_v, *p_w2l=(bf16*)w2l_v, *p_wth=(bf16*)wth_v, *p_wtl=(bf16*)wtl_v;
  float *p_xs=(float*)xs_v, *p_big=(float*)big_v, *p_t=(float*)tb_v, *p_d=(float*)db_v;
  float *p_cs=(float*)cs_v, *p_tf=(float*)tf_v, *p_h1=(float*)h1_v, *p_h2=(float*)h2_v;
  float *p_w1g=(float*)w1gp_v;

  const long SBIG = (long)NP*NP;
  const long SXS  = (long)128*NP;

  // weight planes (deterministic each call)
  to_planes_kernel<<<(1024*512+255)/256, 256>>>(Wf, 1024*512, 512, 512, p_wfh, p_wfl);
  to_planes_kernel<<<(512*512+255)/256, 256>>>(Wc1 + 1024, 512*512, 512, 1536, p_w1h, p_w1l);
  to_planes_kernel<<<(256*512+255)/256, 256>>>(Wc2, 256*512, 512, 512, p_w2h, p_w2l);

  // ---- knn on xyz (fused pdist+topk, one row per block) + edgeconv1 ----
  knn1_kernel<<<NB*NP, 256>>>(x);
  edge_pq_kernel<<<dim3(NP/32, NB), 256>>>(x, -1, (long)3*NP, 3, We1);
  edge_gather_kernel<<<NB*NP, 64>>>(0);
  edge_stats_kernel<<<64, 256>>>((float)((long)NB*NP*KNN));
  bn_relu_kernel<<<(NB*64*NP)/256, 256>>>(1, SXS, 64, 0);

  // ---- knn on f1 (fp32 gram — preserves neighbor selection) + edgeconv2 ----
  sqnorm_kernel<<<(NB*NP)/256, 256>>>();
  gemm_kernel<1, true><<<dim3(16, 32, NB), 256>>>(NP, 64,
      nullptr, 1, NP, SXS, 1, NP, SXS,
      nullptr, 0, NP, SBIG, nullptr, 12, NP, -1, 0);
  topk_kernel<<<NB*NP, 256>>>();
  edge_pq_kernel<<<dim3(NP/32, NB), 256>>>(nullptr, 1, SXS, 64, We2);
  edge_gather_kernel<<<NB*NP, 64>>>(64);
  edge_stats_kernel<<<64, 256>>>((float)((long)NB*NP*KNN));
  bn_relu_kernel<<<(NB*64*NP)/256, 256>>>(1, SXS, 64, 64);

  // xs planes (layer-0 input)
  to_planes_kernel<<<((long)NB*128*NP+255)/256, 256>>>(p_xs, (long)NB*128*NP, NP, NP, p_xsh, p_xsl);

  // ---- 4 SA layers ----
  for (int i = 0; i < 4; i++){
    qk_kernel<<<dim3(NP/32, NB), 256>>>(Wq + (long)i*32*128, Wk + (long)i*32*128,
                                        p_qh, p_ql, p_kh, p_kl);
    // energy = qT @ k  (M=2048, K=32) -> bf16 hi plane only
    mma_gemm<0, 2, true><<<dim3(16, 16, NB), 256>>>(NP, 32,
        p_qh, p_ql, 32, (long)NP*32,
        p_kh, p_kl, (long)32*NP,
        p_big, NP, SBIG,
        p_ah, nullptr, nullptr, 0, nullptr, 0);
    softmax_kernel<<<NB*NP, 256>>>(p_ah);
    colsum_kernel<<<dim3(NP/128, NB), 256>>>(p_ah);
    // y = Wt @ xs  (also emit y planes)
    to_planes_kernel<<<(128*128+255)/256, 256>>>(Wt + (long)i*128*128, 128*128, 128, 128, p_wth, p_wtl);
    mma_gemm<0, 1, true><<<dim3(16, 1, NB), 256>>>(128, 128,
        p_wth, p_wtl, 128, 0,
        p_xsh, p_xsl, SXS,
        p_t, NP, SXS,
        p_yh, p_yl, nullptr, 0, nullptr, 0);
    // t = y - (y @ attn) * cs ; attn hi-only
    mma_gemm<6, 0, false><<<dim3(16, 1, NB), 256>>>(128, NP,
        p_yh, p_yl, NP, SXS,
        p_ah, p_ah, SBIG,
        p_d, NP, SXS,
        nullptr, nullptr, p_t, SXS, p_cs, NP);
    chan_stats_kernel<<<128, 256>>>(p_d, 128, (float)(NB*NP));
    residual_kernel<<<(NB*128*NP)/256, 256>>>(i, p_xsh, p_xsl, p_ch, p_cl);
  }

  // ---- fuse + global max ----
  mma_gemm<0, 0, true><<<dim3(16, 8, NB), 256>>>(1024, 512,
      p_wfh, p_wfl, 512, 0,
      p_ch, p_cl, (long)512*NP,
      p_tf, NP, (long)1024*NP,
      nullptr, nullptr, nullptr, 0, nullptr, 0);
  chan_stats_kernel<<<1024, 256>>>(p_tf, 1024, (float)(NB*NP));
  gmax_kernel<<<NB*1024, 128>>>();
  w1g_kernel<<<64, 256>>>(Wc1);

  // ---- head ----
  mma_gemm<4, 0, true><<<dim3(16, 4, NB), 256>>>(512, 512,
      p_w1h, p_w1l, 512, 0,
      p_ch, p_cl, (long)512*NP,
      p_h1, NP, (long)512*NP,
      nullptr, nullptr, p_w1g, 512, nullptr, 0);
  chan_stats_kernel<<<512, 256>>>(p_h1, 512, (float)(NB*NP));
  bn_relu_planes_kernel<<<((long)NB*512*NP)/256, 256>>>(p_h1, 512, p_h1h, p_h1l);

  mma_gemm<0, 0, true><<<dim3(16, 2, NB), 256>>>(256, 512,
      p_w2h, p_w2l, 512, 0,
      p_h1h, p_h1l, (long)512*NP,
      p_h2, NP, (long)256*NP,
      nullptr, nullptr, nullptr, 0, nullptr, 0);
  chan_stats_kernel<<<256, 256>>>(p_h2, 256, (float)(NB*NP));
  bn_relu_kernel<<<(NB*256*NP)/256, 256>>>(11, (long)256*NP, 256, 0);

  gemm_kernel<5, false><<<dim3(16, 1, NB), 256>>>(13, 256,
      Wc3, -1, 256, 0, 11, NP, (long)256*NP,
      out, -1, NP, (long)13*NP, bc3, -1, 0, -1, 0);
}

// round 17
// speedup vs baseline: 1.8364x; 1.1036x over previous
#include <cuda_runtime.h>
#include <cuda_bf16.h>
#include <cstdint>

#define NB 8
#define NP 2048
#define KNN 32
#define EPSBN 1e-5f
#define NEG_INF -3.402823466e38f

typedef __nv_bfloat16 bf16;

// ----------------- static device scratch (no runtime allocation) -----------------
__device__ float g_big[(size_t)NB*NP*NP];     // pdist2 gram (fp32)
__device__ bf16  g_ah[(size_t)NB*NP*NP];      // energy -> attn (bf16, in-place softmax)
__device__ int   g_idx[(size_t)NB*NP*KNN];
__device__ float g_xx[NB*NP];
__device__ float g_xs[(size_t)NB*128*NP];     // running SA features (fp32)
__device__ bf16  g_xsh[(size_t)NB*128*NP];
__device__ bf16  g_xsl[(size_t)NB*128*NP];
__device__ bf16  g_ch[(size_t)NB*512*NP];     // cat planes
__device__ bf16  g_cl[(size_t)NB*512*NP];
__device__ float g_pt[(size_t)NB*NP*64];
__device__ float g_qt[(size_t)NB*NP*64];
__device__ float g_eps1[(size_t)64*NB*NP];    // stat partials, [o][row] (coalesced read)
__device__ float g_eps2[(size_t)64*NB*NP];
__device__ bf16  g_qh[(size_t)NB*NP*32];      // q^T planes (point-major, lda=32)
__device__ bf16  g_ql[(size_t)NB*NP*32];
__device__ bf16  g_kh[(size_t)NB*32*NP];      // k planes [32][NP]
__device__ bf16  g_kl[(size_t)NB*32*NP];
__device__ float g_d[(size_t)NB*128*NP];      // t pre-BN
__device__ float g_t[(size_t)NB*128*NP];      // y = Wt @ xs (fp32)
__device__ bf16  g_yh[(size_t)NB*128*NP];
__device__ bf16  g_yl[(size_t)NB*128*NP];
__device__ float g_cs[NB*NP];
__device__ float g_tf[(size_t)NB*1024*NP];    // fuse pre-BN
__device__ float g_h1[(size_t)NB*512*NP];
__device__ bf16  g_h1h[(size_t)NB*512*NP];    // relu(bn(h1)) planes
__device__ bf16  g_h1l[(size_t)NB*512*NP];
__device__ float g_h2[(size_t)NB*256*NP];
__device__ float g_gm[NB*1024];
__device__ float g_w1g[NB*512];
__device__ bf16  g_wfh[1024*512]; __device__ bf16 g_wfl[1024*512];
__device__ bf16  g_w1h[512*512];  __device__ bf16 g_w1l[512*512];
__device__ bf16  g_w2h[256*512];  __device__ bf16 g_w2l[256*512];
__device__ bf16  g_wth[128*128];  __device__ bf16 g_wtl[128*128];
__device__ float g_mean[1024];
__device__ float g_istd[1024];

__device__ __forceinline__ float* bsel(int s){
  switch(s){
    case 0: return g_big;  case 1: return g_xs;
    case 11: return g_h2;  case 12: return g_xx;
  }
  return nullptr;
}

// ----------------- deterministic BN stats -----------------
__global__ void edge_stats_kernel(float count){
  int o = blockIdx.x;
  int tid = threadIdx.x;
  __shared__ float sh1[256], sh2[256];
  const float* e1 = g_eps1 + (long)o*(NB*NP);
  const float* e2 = g_eps2 + (long)o*(NB*NP);
  float s1 = 0.f, s2 = 0.f;
  for (int r = tid; r < NB*NP; r += 256){
    s1 += e1[r];
    s2 += e2[r];
  }
  sh1[tid] = s1; sh2[tid] = s2;
  __syncthreads();
  for (int st = 128; st; st >>= 1){
    if (tid < st){ sh1[tid] += sh1[tid+st]; sh2[tid] += sh2[tid+st]; }
    __syncthreads();
  }
  if (tid == 0){
    float m = sh1[0] / count;
    float var = sh2[0] / count - m*m;
    g_mean[o] = m;
    g_istd[o] = rsqrtf(fmaxf(var, 0.f) + EPSBN);
  }
}

__global__ void chan_stats_kernel(const float* __restrict__ src, int C, float count){
  int c = blockIdx.x;
  int tid = threadIdx.x;
  __shared__ float sh1[256], sh2[256];
  float s1 = 0.f, s2 = 0.f;
  for (int b = 0; b < NB; b++){
    const float* p = src + ((long)b*C + c)*NP;
    for (int n = tid; n < NP; n += 256){ float v = p[n]; s1 += v; s2 += v*v; }
  }
  sh1[tid] = s1; sh2[tid] = s2;
  __syncthreads();
  for (int st = 128; st; st >>= 1){
    if (tid < st){ sh1[tid] += sh1[tid+st]; sh2[tid] += sh2[tid+st]; }
    __syncthreads();
  }
  if (tid == 0){
    float m = sh1[0] / count;
    float var = sh2[0] / count - m*m;
    g_mean[c] = m;
    g_istd[c] = rsqrtf(fmaxf(var, 0.f) + EPSBN);
  }
}

// ----------------- small utility kernels -----------------
__global__ void bn_relu_kernel(int dSel, long bstride, int C, int choff){
  float* data = bsel(dSel);
  long i = (long)blockIdx.x*blockDim.x + threadIdx.x;
  long tot = (long)NB*C*NP;
  if (i >= tot) return;
  int n = (int)(i % NP); long t = i / NP;
  int c = (int)(t % C);  int b = (int)(t / C);
  float* p = data + (long)b*bstride + (long)(choff+c)*NP + n;
  float v = (*p - g_mean[c]) * g_istd[c];
  *p = v > 0.f ? v : 0.f;
}

__global__ void bn_relu_planes_kernel(const float* __restrict__ src, int C,
                                      bf16* __restrict__ H, bf16* __restrict__ L){
  long i = (long)blockIdx.x*blockDim.x + threadIdx.x;
  long tot = (long)NB*C*NP;
  if (i >= tot) return;
  int c = (int)((i / NP) % C);
  float v = (src[i] - g_mean[c]) * g_istd[c];
  v = v > 0.f ? v : 0.f;
  bf16 hi = __float2bfloat16(v);
  H[i] = hi; L[i] = __float2bfloat16(v - __bfloat162float(hi));
}

__global__ void to_planes_kernel(const float* __restrict__ src, long total, int cols, int ld,
                                 bf16* __restrict__ H, bf16* __restrict__ L){
  long i = (long)blockIdx.x*256 + threadIdx.x;
  if (i >= total) return;
  long r = i / cols; int c = (int)(i % cols);
  float v = src[r*(long)ld + c];
  bf16 hi = __float2bfloat16(v);
  H[i] = hi; L[i] = __float2bfloat16(v - __bfloat162float(hi));
}

// ----------------- knn -----------------
// fused pdist+topk for xyz: one row per block; sorted-head + winner-warp-only recompute
__global__ void knn1_kernel(const float* __restrict__ x){
  int b = blockIdx.x / NP;
  int n = blockIdx.x % NP;
  __shared__ float sx[3][NP];
  __shared__ float swv[8]; __shared__ int swi[8]; __shared__ int sbi;
  int tid = threadIdx.x;
  int lane = tid & 31, wid = tid >> 5;
  const float* xb = x + (long)b*3*NP;
  for (int i = tid; i < 3*NP; i += 256) sx[i/NP][i%NP] = xb[i];
  __syncthreads();
  float cx = sx[0][n], cy = sx[1][n], cz = sx[2][n];
  float vv[8]; int vi[8];
  #pragma unroll
  for (int i = 0; i < 8; i++){
    int m = tid + i*256;
    float dx = sx[0][m]-cx, dy = sx[1][m]-cy, dz = sx[2][m]-cz;
    vv[i] = -(dx*dx + dy*dy + dz*dz);
    vi[i] = m;
  }
  // sort pairs: value desc, index asc on ties (odd-even transposition, 8 passes)
  #pragma unroll
  for (int pass = 0; pass < 8; pass++){
    #pragma unroll
    for (int i = (pass & 1); i + 1 < 8; i += 2){
      if (vv[i] < vv[i+1] || (vv[i] == vv[i+1] && vi[i] > vi[i+1])){
        float tf = vv[i]; vv[i] = vv[i+1]; vv[i+1] = tf;
        int ti = vi[i]; vi[i] = vi[i+1]; vi[i+1] = ti;
      }
    }
  }
  int* idxout = g_idx + ((long)(b*NP + n))*KNN;
  // initial warp candidates
  {
    float bv = vv[0]; int bi = vi[0];
    #pragma unroll
    for (int off = 16; off; off >>= 1){
      float ov = __shfl_down_sync(0xffffffffu, bv, off);
      int   oi = __shfl_down_sync(0xffffffffu, bi, off);
      if (ov > bv || (ov == bv && oi < bi)){ bv = ov; bi = oi; }
    }
    if (lane == 0){ swv[wid] = bv; swi[wid] = bi; }
  }
  for (int it = 0; it < KNN; it++){
    __syncthreads();
    if (tid == 0){
      float mv = swv[0]; int mi = swi[0];
      #pragma unroll
      for (int w = 1; w < 8; w++)
        if (swv[w] > mv || (swv[w] == mv && swi[w] < mi)){ mv = swv[w]; mi = swi[w]; }
      sbi = mi; idxout[it] = mi;
    }
    __syncthreads();
    int w = sbi;
    if ((w & 255) == tid){
      #pragma unroll
      for (int i = 0; i < 7; i++){ vv[i] = vv[i+1]; vi[i] = vi[i+1]; }
      vv[7] = NEG_INF; vi[7] = 0x7fffffff;
    }
    if (((w & 255) >> 5) == wid){
      float bv = vv[0]; int bi = vi[0];
      #pragma unroll
      for (int off = 16; off; off >>= 1){
        float ov = __shfl_down_sync(0xffffffffu, bv, off);
        int   oi = __shfl_down_sync(0xffffffffu, bi, off);
        if (ov > bv || (ov == bv && oi < bi)){ bv = ov; bi = oi; }
      }
      if (lane == 0){ swv[wid] = bv; swi[wid] = bi; }
    }
  }
}

// topk over fp32 rows of g_big (knn2): same sorted-head protocol
__global__ void topk_kernel(){
  int row = blockIdx.x;
  const float* src = g_big + (long)row*NP;
  int tid = threadIdx.x;
  int lane = tid & 31, wid = tid >> 5;
  __shared__ float swv[8]; __shared__ int swi[8]; __shared__ int sbi;
  float vv[8]; int vi[8];
  #pragma unroll
  for (int i = 0; i < 8; i++){ vv[i] = src[tid + i*256]; vi[i] = tid + i*256; }
  #pragma unroll
  for (int pass = 0; pass < 8; pass++){
    #pragma unroll
    for (int i = (pass & 1); i + 1 < 8; i += 2){
      if (vv[i] < vv[i+1] || (vv[i] == vv[i+1] && vi[i] > vi[i+1])){
        float tf = vv[i]; vv[i] = vv[i+1]; vv[i+1] = tf;
        int ti = vi[i]; vi[i] = vi[i+1]; vi[i+1] = ti;
      }
    }
  }
  int* idxout = g_idx + (long)row*KNN;
  {
    float bv = vv[0]; int bi = vi[0];
    #pragma unroll
    for (int off = 16; off; off >>= 1){
      float ov = __shfl_down_sync(0xffffffffu, bv, off);
      int   oi = __shfl_down_sync(0xffffffffu, bi, off);
      if (ov > bv || (ov == bv && oi < bi)){ bv = ov; bi = oi; }
    }
    if (lane == 0){ swv[wid] = bv; swi[wid] = bi; }
  }
  for (int it = 0; it < KNN; it++){
    __syncthreads();
    if (tid == 0){
      float mv = swv[0]; int mi = swi[0];
      #pragma unroll
      for (int w = 1; w < 8; w++)
        if (swv[w] > mv || (swv[w] == mv && swi[w] < mi)){ mv = swv[w]; mi = swi[w]; }
      sbi = mi; idxout[it] = mi;
    }
    __syncthreads();
    int w = sbi;
    if ((w & 255) == tid){
      #pragma unroll
      for (int i = 0; i < 7; i++){ vv[i] = vv[i+1]; vi[i] = vi[i+1]; }
      vv[7] = NEG_INF; vi[7] = 0x7fffffff;
    }
    if (((w & 255) >> 5) == wid){
      float bv = vv[0]; int bi = vi[0];
      #pragma unroll
      for (int off = 16; off; off >>= 1){
        float ov = __shfl_down_sync(0xffffffffu, bv, off);
        int   oi = __shfl_down_sync(0xffffffffu, bi, off);
        if (ov > bv || (ov == bv && oi < bi)){ bv = ov; bi = oi; }
      }
      if (lane == 0){ swv[wid] = bv; swi[wid] = bi; }
    }
  }
}

// ----------------- edge conv -----------------
__global__ void edge_pq_kernel(const float* __restrict__ fext, int fSel, long fbstride,
                               int C, const float* __restrict__ W){
  const float* f = (fSel >= 0) ? bsel(fSel) : fext;
  int b = blockIdx.y;
  int n0 = blockIdx.x*32;
  const float* fb = f + (long)b*fbstride;
  __shared__ float sf[64][32];
  int nl = threadIdx.x & 31, og = threadIdx.x >> 5;
  for (int c = og; c < C; c += 8) sf[c][nl] = fb[(long)c*NP + n0 + nl];
  __syncthreads();
  #pragma unroll
  for (int j = 0; j < 8; j++){
    int o = og*8 + j;
    const float* w = W + (long)o*2*C;
    float ap = 0.f, aq = 0.f;
    for (int c = 0; c < C; c++){
      float fv = sf[c][nl];
      ap += w[c]*fv;
      aq += (w[C+c]-w[c])*fv;
    }
    long off = ((long)(b*NP + n0 + nl))*64 + o;
    g_pt[off] = ap; g_qt[off] = aq;
  }
}

__global__ void edge_gather_kernel(int chbase){
  int row = blockIdx.x; int b = row / NP, n = row % NP;
  int o = threadIdx.x;
  __shared__ int sidx[KNN];
  if (o < KNN) sidx[o] = g_idx[(long)row*KNN + o];
  __syncthreads();
  float q = g_qt[(long)row*64 + o];
  float mx = NEG_INF, s1 = 0.f, s2 = 0.f;
  const float* pb = g_pt + (long)b*NP*64;
  #pragma unroll 4
  for (int k = 0; k < KNN; k++){
    float v = pb[(long)sidx[k]*64 + o] + q;
    mx = fmaxf(mx, v); s1 += v; s2 += v*v;
  }
  g_xs[((long)b*128 + chbase + o)*NP + n] = mx;
  g_eps1[(long)o*(NB*NP) + row] = s1;
  g_eps2[(long)o*(NB*NP) + row] = s2;
}

__global__ void sqnorm_kernel(){
  int i = blockIdx.x*blockDim.x + threadIdx.x;
  if (i >= NB*NP) return;
  int b = i / NP, n = i % NP;
  const float* f = g_xs + (long)b*128*NP + n;
  float s = 0.f;
  #pragma unroll 8
  for (int c = 0; c < 64; c++){ float v = f[(long)c*NP]; s += v*v; }
  g_xx[i] = s;
}

// ----------------- SA layer helpers -----------------
__global__ void qk_kernel(const float* __restrict__ Wq, const float* __restrict__ Wk,
                          bf16* __restrict__ qTh, bf16* __restrict__ qTl,
                          bf16* __restrict__ kh, bf16* __restrict__ kl){
  int b = blockIdx.y, n0 = blockIdx.x*32;
  __shared__ float sf[128][32];
  int nl = threadIdx.x & 31, og = threadIdx.x >> 5;
  const float* xb = g_xs + (long)b*128*NP;
  for (int c = og; c < 128; c += 8) sf[c][nl] = xb[(long)c*NP + n0 + nl];
  __syncthreads();
  #pragma unroll
  for (int j = 0; j < 4; j++){
    int qi = og*4 + j;
    const float* wq = Wq + qi*128;
    const float* wk = Wk + qi*128;
    float aq = 0.f, ak = 0.f;
    for (int c = 0; c < 128; c++){
      float fv = sf[c][nl];
      aq += wq[c]*fv; ak += wk[c]*fv;
    }
    bf16 qh = __float2bfloat16(aq);
    bf16 ql = __float2bfloat16(aq - __bfloat162float(qh));
    bf16 kh2 = __float2bfloat16(ak);
    bf16 kl2 = __float2bfloat16(ak - __bfloat162float(kh2));
    long qoff = ((long)b*NP + n0 + nl)*32 + qi;
    qTh[qoff] = qh; qTl[qoff] = ql;
    long koff = ((long)b*32 + qi)*NP + n0 + nl;
    kh[koff] = kh2; kl[koff] = kl2;
  }
}

// softmax IN PLACE on bf16 energy rows -> bf16 attn rows
__global__ void softmax_kernel(bf16* __restrict__ ah){
  long row = blockIdx.x;
  bf16* p = ah + row*(long)NP;
  int tid = threadIdx.x;
  int lane = tid & 31, wid = tid >> 5;
  __shared__ float sred[8];
  __shared__ float sres;
  float v[8];
  #pragma unroll
  for (int i = 0; i < 8; i++) v[i] = __bfloat162float(p[tid + i*256]);
  float m = v[0];
  #pragma unroll
  for (int i = 1; i < 8; i++) m = fmaxf(m, v[i]);
  #pragma unroll
  for (int off = 16; off; off >>= 1) m = fmaxf(m, __shfl_xor_sync(0xffffffffu, m, off));
  if (lane == 0) sred[wid] = m;
  __syncthreads();
  if (tid == 0){
    float t = sred[0];
    #pragma unroll
    for (int w = 1; w < 8; w++) t = fmaxf(t, sred[w]);
    sres = t;
  }
  __syncthreads();
  float bmax = sres;
  float s = 0.f;
  #pragma unroll
  for (int i = 0; i < 8; i++){ v[i] = __expf(v[i] - bmax); s += v[i]; }
  #pragma unroll
  for (int off = 16; off; off >>= 1) s += __shfl_xor_sync(0xffffffffu, s, off);
  __syncthreads();
  if (lane == 0) sred[wid] = s;
  __syncthreads();
  if (tid == 0){
    float t = 0.f;
    #pragma unroll
    for (int w = 0; w < 8; w++) t += sred[w];
    sres = t;
  }
  __syncthreads();
  float inv = 1.f / sres;
  #pragma unroll
  for (int i = 0; i < 8; i++)
    p[tid + i*256] = __float2bfloat16(v[i]*inv);
}

// column sums of attn: 128 columns per block, 4-way n-split, fixed-order combine
__global__ void colsum_kernel(const bf16* __restrict__ ah){
  int b = blockIdx.y;
  int cp = threadIdx.x & 63;
  int ns = threadIdx.x >> 6;
  int m2 = blockIdx.x*64 + cp;
  const __nv_bfloat162* A = (const __nv_bfloat162*)(ah + (long)b*NP*NP) + m2;
  float s0 = 0.f, s1 = 0.f;
  int nbeg = ns*512, nend = nbeg + 512;
  for (int n = nbeg; n < nend; n++){
    float2 f = __bfloat1622float2(A[(long)n*(NP/2)]);
    s0 += f.x; s1 += f.y;
  }
  __shared__ float sh[4][64][2];
  sh[ns][cp][0] = s0; sh[ns][cp][1] = s1;
  __syncthreads();
  if (ns == 0){
    float t0 = (sh[0][cp][0] + sh[1][cp][0]) + (sh[2][cp][0] + sh[3][cp][0]);
    float t1 = (sh[0][cp][1] + sh[1][cp][1]) + (sh[2][cp][1] + sh[3][cp][1]);
    g_cs[b*NP + 2*m2    ] = 1.f / (1e-6f + t0);
    g_cs[b*NP + 2*m2 + 1] = 1.f / (1e-6f + t1);
  }
}

// residual: xs += relu(bn(t)); write xs planes + cat plane slice
__global__ void residual_kernel(int layer,
                                bf16* __restrict__ xsh, bf16* __restrict__ xsl,
                                bf16* __restrict__ ch, bf16* __restrict__ cl){
  long i = (long)blockIdx.x*blockDim.x + threadIdx.x;
  long tot = (long)NB*128*NP;
  if (i >= tot) return;
  int n = (int)(i % NP); long t = i / NP;
  int c = (int)(t % 128); int b = (int)(t / 128);
  long xi = ((long)b*128 + c)*NP + n;
  float tv = g_d[xi];
  float r = (tv - g_mean[c]) * g_istd[c];
  r = r > 0.f ? r : 0.f;
  float v = g_xs[xi] + r;
  g_xs[xi] = v;
  bf16 hi = __float2bfloat16(v);
  bf16 lo = __float2bfloat16(v - __bfloat162float(hi));
  xsh[xi] = hi; xsl[xi] = lo;
  long ci = ((long)b*512 + layer*128 + c)*NP + n;
  ch[ci] = hi; cl[ci] = lo;
}

// ----------------- fuse / head helpers -----------------
__global__ void gmax_kernel(){
  int row = blockIdx.x;
  int o = row & 1023;
  const float* p = g_tf + (long)row*NP;
  float m = NEG_INF;
  for (int n = threadIdx.x; n < NP; n += 128) m = fmaxf(m, p[n]);
  #pragma unroll
  for (int off = 16; off; off >>= 1) m = fmaxf(m, __shfl_xor_sync(0xffffffffu, m, off));
  __shared__ float sw[4];
  int lane = threadIdx.x & 31, wid = threadIdx.x >> 5;
  if (lane == 0) sw[wid] = m;
  __syncthreads();
  if (threadIdx.x == 0){
    float mm = fmaxf(fmaxf(sw[0], sw[1]), fmaxf(sw[2], sw[3]));
    float v = (mm - g_mean[o]) * g_istd[o];
    g_gm[row] = v > 0.f ? v : 0.f;
  }
}

__global__ void w1g_kernel(const float* __restrict__ Wc1){
  int o = blockIdx.x*8 + (threadIdx.x >> 5);
  int lane = threadIdx.x & 31;
  const float* w = Wc1 + (long)o*1536;
  float acc[NB];
  #pragma unroll
  for (int b = 0; b < NB; b++) acc[b] = 0.f;
  for (int c = lane; c < 1024; c += 32){
    float wv = w[c];
    #pragma unroll
    for (int b = 0; b < NB; b++) acc[b] += wv * g_gm[b*1024 + c];
  }
  #pragma unroll
  for (int b = 0; b < NB; b++){
    #pragma unroll
    for (int off = 16; off; off >>= 1) acc[b] += __shfl_xor_sync(0xffffffffu, acc[b], off);
  }
  if (lane == 0){
    #pragma unroll
    for (int b = 0; b < NB; b++) g_w1g[b*512 + o] = acc[b];
  }
}

// ----------------- tensor-core bf16-split GEMM -----------------
__device__ __forceinline__ uint32_t smem_u32(const void* p){
  return (uint32_t)__cvta_generic_to_shared(p);
}
__device__ __forceinline__ void ldm_x4(uint32_t a, uint32_t &r0, uint32_t &r1, uint32_t &r2, uint32_t &r3){
  asm volatile("ldmatrix.sync.aligned.m8n8.x4.shared.b16 {%0,%1,%2,%3}, [%4];"
    : "=r"(r0),"=r"(r1),"=r"(r2),"=r"(r3) : "r"(a));
}
__device__ __forceinline__ void ldm_x4t(uint32_t a, uint32_t &r0, uint32_t &r1, uint32_t &r2, uint32_t &r3){
  asm volatile("ldmatrix.sync.aligned.m8n8.x4.trans.shared.b16 {%0,%1,%2,%3}, [%4];"
    : "=r"(r0),"=r"(r1),"=r"(r2),"=r"(r3) : "r"(a));
}
__device__ __forceinline__ void mma16816(float* d, const uint32_t* a, const uint32_t* b){
  asm volatile("mma.sync.aligned.m16n8k16.row.col.f32.bf16.bf16.f32 "
    "{%0,%1,%2,%3}, {%4,%5,%6,%7}, {%8,%9}, {%0,%1,%2,%3};"
    : "+f"(d[0]),"+f"(d[1]),"+f"(d[2]),"+f"(d[3])
    : "r"(a[0]),"r"(a[1]),"r"(a[2]),"r"(a[3]), "r"(b[0]),"r"(b[1]));
}

// C[b](M x 2048) = A[b](M x K, hi/lo planes, lda) * B[b](K x 2048, ldb=NP)
// EPI: 0 plain, 4 rowbias(E1[b][row]), 6 xr: v=E1[row*NP+col]-a*E2[col]
// POUT: 0 = fp32 C only; 1 = fp32 C + bf16 hi/lo planes; 2 = bf16 hi plane ONLY
// BLO: B has a lo plane (3-product split) or hi only (2 products)
template<int EPI, int POUT, bool BLO>
__global__ void __launch_bounds__(256)
mma_gemm(int M, int K,
  const bf16* __restrict__ Ah, const bf16* __restrict__ Al, int lda, long sA,
  const bf16* __restrict__ Bh, const bf16* __restrict__ Bl, long sB,
  float* __restrict__ Cc, int ldc, long sC,
  bf16* __restrict__ Ph, bf16* __restrict__ Pl,
  const float* __restrict__ E1, long se1,
  const float* __restrict__ E2, long se2)
{
  __shared__ bf16 As[2][128][40];
  __shared__ bf16 Bs[BLO ? 2 : 1][32][136];
  int bb = blockIdx.z;
  const bf16* Ap[2] = {Ah + (long)bb*sA, Al + (long)bb*sA};
  const bf16* Bp0 = Bh + (long)bb*sB;
  const bf16* Bp1 = BLO ? (Bl + (long)bb*sB) : nullptr;
  float* C = Cc + (long)bb*sC;
  const float* e1 = nullptr; const float* e2 = nullptr;
  if (EPI == 4 || EPI == 6) e1 = E1 + (long)bb*se1;
  if (EPI == 6) e2 = E2 + (long)bb*se2;

  int tm = blockIdx.y*128, tn = blockIdx.x*128;
  int tid = threadIdx.x, lane = tid & 31, wid = tid >> 5;
  int wm = wid >> 2, wn = wid & 3;

  float acc[4][4][4];
  #pragma unroll
  for (int i = 0; i < 4; i++)
    #pragma unroll
    for (int j = 0; j < 4; j++)
      #pragma unroll
      for (int u = 0; u < 4; u++) acc[i][j][u] = 0.f;

  int fr = lane & 15, fs = lane >> 4;

  for (int k0 = 0; k0 < K; k0 += 32){
    #pragma unroll
    for (int l = 0; l < 4; l++){
      int li = tid + l*256;
      int p = li >> 9, s = li & 511;
      int r = s >> 2, seg = (s & 3)*8;
      uint4 v = *(const uint4*)&Ap[p][(long)(tm + r)*lda + k0 + seg];
      *(uint4*)&As[p][r][seg] = v;
    }
    {
      constexpr int NBL = BLO ? 4 : 2;
      #pragma unroll
      for (int l = 0; l < NBL; l++){
        int li = tid + l*256;
        int p = li >> 9, s = li & 511;
        int kk = s >> 4, seg = (s & 15)*8;
        const bf16* src = (p == 0) ? Bp0 : Bp1;
        uint4 v = *(const uint4*)&src[(long)(k0 + kk)*NP + tn + seg];
        *(uint4*)&Bs[p][kk][seg] = v;
      }
    }
    __syncthreads();
    #pragma unroll
    for (int ks = 0; ks < 2; ks++){
      uint32_t aF[2][4][4], bF[2][4][2];
      #pragma unroll
      for (int p = 0; p < 2; p++){
        #pragma unroll
        for (int i = 0; i < 4; i++){
          uint32_t ad = smem_u32(&As[p][wm*64 + i*16 + fr][ks*16 + fs*8]);
          ldm_x4(ad, aF[p][i][0], aF[p][i][1], aF[p][i][2], aF[p][i][3]);
        }
      }
      constexpr int NBP = BLO ? 2 : 1;
      #pragma unroll
      for (int p = 0; p < NBP; p++){
        #pragma unroll
        for (int j2 = 0; j2 < 2; j2++){
          uint32_t ad = smem_u32(&Bs[p][ks*16 + fr][wn*32 + j2*16 + fs*8]);
          ldm_x4t(ad, bF[p][j2*2][0], bF[p][j2*2][1], bF[p][j2*2+1][0], bF[p][j2*2+1][1]);
        }
      }
      #pragma unroll
      for (int i = 0; i < 4; i++)
        #pragma unroll
        for (int j = 0; j < 4; j++){
          mma16816(acc[i][j], aF[0][i], bF[0][j]);
          if (BLO) mma16816(acc[i][j], aF[0][i], bF[1][j]);
          mma16816(acc[i][j], aF[1][i], bF[0][j]);
        }
    }
    __syncthreads();
  }

  int gr = lane >> 2, cp = (lane & 3)*2;
  #pragma unroll
  for (int i = 0; i < 4; i++){
    #pragma unroll
    for (int h = 0; h < 2; h++){
      int row = tm + wm*64 + i*16 + gr + h*8;
      float rowbias = (EPI == 4) ? e1[row] : 0.f;
      #pragma unroll
      for (int j = 0; j < 4; j++){
        int col = tn + wn*32 + j*8 + cp;
        #pragma unroll
        for (int u = 0; u < 2; u++){
          float v = acc[i][j][h*2 + u];
          int cc = col + u;
          if (EPI == 6) v = e1[(long)row*NP + cc] - v*e2[cc];
          else v += rowbias;
          if (POUT != 2) C[(long)row*ldc + cc] = v;
          if (POUT == 1){
            bf16 hi = __float2bfloat16(v);
            long po = (long)bb*sC + (long)row*ldc + cc;
            Ph[po] = hi; Pl[po] = __float2bfloat16(v - __bfloat162float(hi));
          } else if (POUT == 2){
            long po = (long)bb*sC + (long)row*ldc + cc;
            Ph[po] = __float2bfloat16(v);
          }
        }
      }
    }
  }
}

// ----------------- fp32 tiled SGEMM (pdist2 gram + final Wc3 only) -----------------
template<int EPI, bool TRANSA>
__global__ void __launch_bounds__(256)
gemm_kernel(int M, int K,
  const float* __restrict__ Aext, int aSel, int lda, long sA,
  int bSel, int ldb, long sB,
  float* __restrict__ Cext, int cSel, int ldc, long sC,
  const float* __restrict__ e1ext, int e1Sel, long se1,
  int e2Sel, long se2)
{
  int bb = blockIdx.z;
  const float* A = ((aSel >= 0) ? bsel(aSel) : Aext) + (long)bb*sA;
  const float* B = bsel(bSel) + (long)bb*sB;
  float* C = ((cSel >= 0) ? bsel(cSel) : Cext) + (long)bb*sC;
  const float* E1 = nullptr;
  if (EPI == 1 || EPI == 5)
    E1 = ((e1Sel >= 0) ? bsel(e1Sel) : e1ext) + (long)bb*se1;

  int tm = blockIdx.y*64, tn = blockIdx.x*128;
  __shared__ float As[32][68];
  __shared__ float Bs[32][128];
  int tid = threadIdx.x;
  int tx = tid & 15, ty = tid >> 4;
  float acc[4][8] = {};

  for (int k0 = 0; k0 < K; k0 += 32){
    if (TRANSA){
      int kk = tid >> 4, mm = (tid & 15)*4;
      *(float4*)&As[kk   ][mm] = *(const float4*)&A[(long)(k0+kk   )*lda + tm + mm];
      *(float4*)&As[kk+16][mm] = *(const float4*)&A[(long)(k0+kk+16)*lda + tm + mm];
    } else {
      int rl = tid >> 2, kk = (tid & 3)*8;
      int row = tm + rl;
      float4 a0 = make_float4(0.f,0.f,0.f,0.f), a1 = a0;
      if (row < M){
        a0 = *(const float4*)&A[(long)row*lda + k0 + kk];
        a1 = *(const float4*)&A[(long)row*lda + k0 + kk + 4];
      }
      As[kk  ][rl] = a0.x; As[kk+1][rl] = a0.y; As[kk+2][rl] = a0.z; As[kk+3][rl] = a0.w;
      As[kk+4][rl] = a1.x; As[kk+5][rl] = a1.y; As[kk+6][rl] = a1.z; As[kk+7][rl] = a1.w;
    }
    {
      int kb = tid >> 4, nn = (tid & 15)*4;
      *(float4*)&Bs[kb   ][nn   ] = *(const float4*)&B[(long)(k0+kb   )*ldb + tn + nn];
      *(float4*)&Bs[kb   ][nn+64] = *(const float4*)&B[(long)(k0+kb   )*ldb + tn + nn + 64];
      *(float4*)&Bs[kb+16][nn   ] = *(const float4*)&B[(long)(k0+kb+16)*ldb + tn + nn];
      *(float4*)&Bs[kb+16][nn+64] = *(const float4*)&B[(long)(k0+kb+16)*ldb + tn + nn + 64];
    }
    __syncthreads();
    #pragma unroll
    for (int kk = 0; kk < 32; kk++){
      float4 a4 = *(float4*)&As[kk][ty*4];
      float4 b0 = *(float4*)&Bs[kk][tx*4];
      float4 b1 = *(float4*)&Bs[kk][64 + tx*4];
      float ar[4] = {a4.x, a4.y, a4.z, a4.w};
      float br[8] = {b0.x, b0.y, b0.z, b0.w, b1.x, b1.y, b1.z, b1.w};
      #pragma unroll
      for (int i = 0; i < 4; i++)
        #pragma unroll
        for (int j = 0; j < 8; j++)
          acc[i][j] += ar[i]*br[j];
    }
    __syncthreads();
  }

  int c0 = tn + tx*4, c1 = tn + 64 + tx*4;
  #pragma unroll
  for (int i = 0; i < 4; i++){
    int row = tm + ty*4 + i;
    bool ok = row < M;
    float bias = 0.f;
    if (EPI == 5 && ok) bias = E1[row];
    float out[8];
    #pragma unroll
    for (int j = 0; j < 8; j++){
      int col = (j < 4) ? (c0 + j) : (c1 + j - 4);
      float v = acc[i][j];
      if (EPI == 1) v = 2.f*v - (ok ? E1[row] : 0.f) - E1[col];
      else          v += bias;
      out[j] = v;
    }
    if (ok){
      *(float4*)&C[(long)row*ldc + c0] = make_float4(out[0],out[1],out[2],out[3]);
      *(float4*)&C[(long)row*ldc + c1] = make_float4(out[4],out[5],out[6],out[7]);
    }
  }
}

// ----------------- host orchestration -----------------
#define SYMADDR(var, sym) void* var##_v; cudaGetSymbolAddress(&var##_v, sym);
extern "C" void kernel_launch(void* const* d_in, const int* in_sizes, int n_in,
                              void* d_out, int out_size) {
  (void)in_sizes; (void)n_in; (void)out_size;
  const float* x   = (const float*)d_in[0];
  const float* We1 = (const float*)d_in[1];
  const float* We2 = (const float*)d_in[3];
  const float* Wq  = (const float*)d_in[5];
  const float* Wk  = (const float*)d_in[6];
  const float* Wt  = (const float*)d_in[7];
  const float* Wf  = (const float*)d_in[9];
  const float* Wc1 = (const float*)d_in[11];
  const float* Wc2 = (const float*)d_in[13];
  const float* Wc3 = (const float*)d_in[15];
  const float* bc3 = (const float*)d_in[16];
  float* out = (float*)d_out;

  SYMADDR(ah, g_ah)
  SYMADDR(xsh, g_xsh) SYMADDR(xsl, g_xsl)
  SYMADDR(ch, g_ch)   SYMADDR(cl, g_cl)
  SYMADDR(qh, g_qh)   SYMADDR(ql, g_ql)
  SYMADDR(kh, g_kh)   SYMADDR(kl, g_kl)
  SYMADDR(yh, g_yh)   SYMADDR(yl, g_yl)
  SYMADDR(h1h, g_h1h) SYMADDR(h1l, g_h1l)
  SYMADDR(wfh, g_wfh) SYMADDR(wfl, g_wfl)
  SYMADDR(w1h, g_w1h) SYMADDR(w1l, g_w1l)
  SYMADDR(w2h, g_w2h) SYMADDR(w2l, g_w2l)
  SYMADDR(wth, g_wth) SYMADDR(wtl, g_wtl)
  SYMADDR(xs, g_xs)   SYMADDR(big, g_big)
  SYMADDR(tb, g_t)    SYMADDR(db, g_d)
  SYMADDR(cs, g_cs)   SYMADDR(tf, g_tf)
  SYMADDR(h1, g_h1)   SYMADDR(h2, g_h2)
  SYMADDR(w1gp, g_w1g)
  bf16 *p_ah=(bf16*)ah_v, *p_xsh=(bf16*)xsh_v, *p_xsl=(bf16*)xsl_v;
  bf16 *p_ch=(bf16*)ch_v, *p_cl=(bf16*)cl_v, *p_qh=(bf16*)qh_v, *p_ql=(bf16*)ql_v;
  bf16 *p_kh=(bf16*)kh_v, *p_kl=(bf16*)kl_v;
  bf16 *p_yh=(bf16*)yh_v, *p_yl=(bf16*)yl_v, *p_h1h=(bf16*)h1h_v, *p_h1l=(bf16*)h1l_v;
  bf16 *p_wfh=(bf16*)wfh_v, *p_wfl=(bf16*)wfl_v, *p_w1h=(bf16*)w1h_v, *p_w1l=(bf16*)w1l_v;
  bf16 *p_w2h=(bf16*)w2h_v, *p_w2l=(bf16*)w2l_v, *p_wth=(bf16*)wth_v, *p_wtl=(bf16*)wtl_v;
  float *p_xs=(float*)xs_v, *p_big=(float*)big_v, *p_t=(float*)tb_v, *p_d=(float*)db_v;
  float *p_cs=(float*)cs_v, *p_tf=(float*)tf_v, *p_h1=(float*)h1_v, *p_h2=(float*)h2_v;
  float *p_w1g=(float*)w1gp_v;

  const long SBIG = (long)NP*NP;
  const long SXS  = (long)128*NP;

  // weight planes (deterministic each call)
  to_planes_kernel<<<(1024*512+255)/256, 256>>>(Wf, 1024*512, 512, 512, p_wfh, p_wfl);
  to_planes_kernel<<<(512*512+255)/256, 256>>>(Wc1 + 1024, 512*512, 512, 1536, p_w1h, p_w1l);
  to_planes_kernel<<<(256*512+255)/256, 256>>>(Wc2, 256*512, 512, 512, p_w2h, p_w2l);

  // ---- knn on xyz (fused pdist+topk, one row per block) + edgeconv1 ----
  knn1_kernel<<<NB*NP, 256>>>(x);
  edge_pq_kernel<<<dim3(NP/32, NB), 256>>>(x, -1, (long)3*NP, 3, We1);
  edge_gather_kernel<<<NB*NP, 64>>>(0);
  edge_stats_kernel<<<64, 256>>>((float)((long)NB*NP*KNN));
  bn_relu_kernel<<<(NB*64*NP)/256, 256>>>(1, SXS, 64, 0);

  // ---- knn on f1 (fp32 gram — preserves neighbor selection) + edgeconv2 ----
  sqnorm_kernel<<<(NB*NP)/256, 256>>>();
  gemm_kernel<1, true><<<dim3(16, 32, NB), 256>>>(NP, 64,
      nullptr, 1, NP, SXS, 1, NP, SXS,
      nullptr, 0, NP, SBIG, nullptr, 12, NP, -1, 0);
  topk_kernel<<<NB*NP, 256>>>();
  edge_pq_kernel<<<dim3(NP/32, NB), 256>>>(nullptr, 1, SXS, 64, We2);
  edge_gather_kernel<<<NB*NP, 64>>>(64);
  edge_stats_kernel<<<64, 256>>>((float)((long)NB*NP*KNN));
  bn_relu_kernel<<<(NB*64*NP)/256, 256>>>(1, SXS, 64, 64);

  // xs planes (layer-0 input)
  to_planes_kernel<<<((long)NB*128*NP+255)/256, 256>>>(p_xs, (long)NB*128*NP, NP, NP, p_xsh, p_xsl);

  // ---- 4 SA layers ----
  for (int i = 0; i < 4; i++){
    qk_kernel<<<dim3(NP/32, NB), 256>>>(Wq + (long)i*32*128, Wk + (long)i*32*128,
                                        p_qh, p_ql, p_kh, p_kl);
    // energy = qT @ k  (M=2048, K=32) -> bf16 hi plane only
    mma_gemm<0, 2, true><<<dim3(16, 16, NB), 256>>>(NP, 32,
        p_qh, p_ql, 32, (long)NP*32,
        p_kh, p_kl, (long)32*NP,
        p_big, NP, SBIG,
        p_ah, nullptr, nullptr, 0, nullptr, 0);
    softmax_kernel<<<NB*NP, 256>>>(p_ah);
    colsum_kernel<<<dim3(NP/128, NB), 256>>>(p_ah);
    // y = Wt @ xs  (also emit y planes)
    to_planes_kernel<<<(128*128+255)/256, 256>>>(Wt + (long)i*128*128, 128*128, 128, 128, p_wth, p_wtl);
    mma_gemm<0, 1, true><<<dim3(16, 1, NB), 256>>>(128, 128,
        p_wth, p_wtl, 128, 0,
        p_xsh, p_xsl, SXS,
        p_t, NP, SXS,
        p_yh, p_yl, nullptr, 0, nullptr, 0);
    // t = y - (y @ attn) * cs ; attn hi-only
    mma_gemm<6, 0, false><<<dim3(16, 1, NB), 256>>>(128, NP,
        p_yh, p_yl, NP, SXS,
        p_ah, p_ah, SBIG,
        p_d, NP, SXS,
        nullptr, nullptr, p_t, SXS, p_cs, NP);
    chan_stats_kernel<<<128, 256>>>(p_d, 128, (float)(NB*NP));
    residual_kernel<<<(NB*128*NP)/256, 256>>>(i, p_xsh, p_xsl, p_ch, p_cl);
  }

  // ---- fuse + global max ----
  mma_gemm<0, 0, true><<<dim3(16, 8, NB), 256>>>(1024, 512,
      p_wfh, p_wfl, 512, 0,
      p_ch, p_cl, (long)512*NP,
      p_tf, NP, (long)1024*NP,
      nullptr, nullptr, nullptr, 0, nullptr, 0);
  chan_stats_kernel<<<1024, 256>>>(p_tf, 1024, (float)(NB*NP));
  gmax_kernel<<<NB*1024, 128>>>();
  w1g_kernel<<<64, 256>>>(Wc1);

  // ---- head ----
  mma_gemm<4, 0, true><<<dim3(16, 4, NB), 256>>>(512, 512,
      p_w1h, p_w1l, 512, 0,
      p_ch, p_cl, (long)512*NP,
      p_h1, NP, (long)512*NP,
      nullptr, nullptr, p_w1g, 512, nullptr, 0);
  chan_stats_kernel<<<512, 256>>>(p_h1, 512, (float)(NB*NP));
  bn_relu_planes_kernel<<<((long)NB*512*NP)/256, 256>>>(p_h1, 512, p_h1h, p_h1l);

  mma_gemm<0, 0, true><<<dim3(16, 2, NB), 256>>>(256, 512,
      p_w2h, p_w2l, 512, 0,
      p_h1h, p_h1l, (long)512*NP,
      p_h2, NP, (long)256*NP,
      nullptr, nullptr, nullptr, 0, nullptr, 0);
  chan_stats_kernel<<<256, 256>>>(p_h2, 256, (float)(NB*NP));
  bn_relu_kernel<<<(NB*256*NP)/256, 256>>>(11, (long)256*NP, 256, 0);

  gemm_kernel<5, false><<<dim3(16, 1, NB), 256>>>(13, 256,
      Wc3, -1, 256, 0, 11, NP, (long)256*NP,
      out, -1, NP, (long)13*NP, bc3, -1, 0, -1, 0);
}